// round 7
// baseline (speedup 1.0000x reference)
#include <cuda_runtime.h>
#include <cstdint>

#define VV 49152
#define NNZ 9
#define GN_N 393216.0f  // V * (C/G) = 49152 * 8

// ---------------- scratch (device globals; no runtime allocation) ----------------
__device__ float d_T[(size_t)8 * VV * 64];    // block1 Chebyshev terms 1..7 (slot 0 unused)
__device__ float d_U[(size_t)8 * VV * 128];   // slot0 = h1pre (raw), slots 1..7 = block2 terms
__device__ float d_res[(size_t)2 * VV * 64];  // residual conv output [b][v][o]
__device__ float d_stats[64];                 // [0:32) GN1 (sum,sumsq)x16, [32:64) GN2
__device__ float d_Bt1[8 * 128 * 32];         // GEMM1 B^T (W1|Wr), tf32-rounded
__device__ float d_Bt2[16 * 64 * 32];         // GEMM2 B^T (W2), tf32-rounded

// ---------------- helpers ----------------
__device__ __forceinline__ float ftf32(float x) {
    uint32_t r;
    asm("cvt.rna.tf32.f32 %0, %1;" : "=r"(r) : "f"(x));
    return __uint_as_float(r);
}
__device__ __forceinline__ void mma_tf32(float* d, uint32_t a0, uint32_t a1, uint32_t a2,
                                         uint32_t a3, uint32_t b0, uint32_t b1) {
    asm volatile(
        "mma.sync.aligned.m16n8k8.row.col.f32.tf32.tf32.f32 "
        "{%0,%1,%2,%3}, {%4,%5,%6,%7}, {%8,%9}, {%0,%1,%2,%3};"
        : "+f"(d[0]), "+f"(d[1]), "+f"(d[2]), "+f"(d[3])
        : "r"(a0), "r"(a1), "r"(a2), "r"(a3), "r"(b0), "r"(b1));
}
// GN1 scale/shift for 4 consecutive channels c0..c0+3 (must share group g=c0>>3).
__device__ __forceinline__ void gn1_params(int b, int c0,
                                           const float* __restrict__ gamma,
                                           const float* __restrict__ beta,
                                           float4& scl, float4& sft) {
    int bin = (b * 8 + (c0 >> 3)) * 2;
    float mu = d_stats[bin] / GN_N;
    float var = d_stats[bin + 1] / GN_N - mu * mu;
    float rstd = rsqrtf(var + 1e-5f);
    scl.x = rstd * __ldg(&gamma[c0 + 0]); sft.x = __ldg(&beta[c0 + 0]) - mu * scl.x;
    scl.y = rstd * __ldg(&gamma[c0 + 1]); sft.y = __ldg(&beta[c0 + 1]) - mu * scl.y;
    scl.z = rstd * __ldg(&gamma[c0 + 2]); sft.z = __ldg(&beta[c0 + 2]) - mu * scl.z;
    scl.w = rstd * __ldg(&gamma[c0 + 3]); sft.w = __ldg(&beta[c0 + 3]) - mu * scl.w;
}
__device__ __forceinline__ float lk(float y) { return fmaxf(y, 0.1f * y); }

// ---------------- small kernels ----------------
__global__ void k_zero_stats() {
    if (threadIdx.x < 64) d_stats[threadIdx.x] = 0.0f;
}

// Pre-transpose weights into [o][k] layout, tf32-rounded.
__global__ void k_wtrans(const float* __restrict__ W1, const float* __restrict__ Wr,
                         const float* __restrict__ W2) {
    int idx = blockIdx.x * blockDim.x + threadIdx.x;
    if (idx < 8 * 128 * 32) {
        int kk = idx >> 12, r = idx & 4095, o = r >> 5, f = r & 31;
        float w = (o < 64) ? W1[kk * 2048 + f * 64 + o] : Wr[kk * 2048 + f * 64 + (o - 64)];
        d_Bt1[idx] = ftf32(w);
    } else if (idx < 8 * 128 * 32 + 16 * 64 * 32) {
        int j = idx - 8 * 128 * 32;
        int c = j >> 11, rr = j & 2047, o = rr >> 5, f = rr & 31;
        int kk = c >> 1, f0 = (c & 1) * 32;
        d_Bt2[j] = ftf32(W2[kk * 4096 + (f0 + f) * 64 + o]);
    }
}

// ---------------- block1 SPMM family (D=64, 4 floats/thread) ----------------
// t1 = L x  (gather straight from x; x layout [b][v][32])
__global__ void __launch_bounds__(256) k_spmm1_first(const float* __restrict__ x,
                                                     const float* __restrict__ vals,
                                                     const int* __restrict__ cols) {
    int tid = blockIdx.x * 256 + threadIdx.x;
    int v = tid >> 4, d4 = tid & 15;
    int b = d4 >> 3, f4 = d4 & 7;
    const float4* xs = (const float4*)x;
    size_t xbase = (size_t)b * VV * 8 + f4;
    float4 acc = make_float4(0.f, 0.f, 0.f, 0.f);
#pragma unroll
    for (int j = 0; j < NNZ; ++j) {
        int c = __ldg(&cols[v * NNZ + j]);
        float w = __ldg(&vals[v * NNZ + j]);
        float4 t = __ldg(&xs[xbase + (size_t)c * 8]);
        acc.x += w * t.x; acc.y += w * t.y; acc.z += w * t.z; acc.w += w * t.w;
    }
    ((float4*)(d_T + (size_t)1 * VV * 64))[tid] = acc;
}

// t2 = 2 L t1 - x
__global__ void __launch_bounds__(256) k_spmm1_second(const float* __restrict__ x,
                                                      const float* __restrict__ vals,
                                                      const int* __restrict__ cols) {
    int tid = blockIdx.x * 256 + threadIdx.x;
    int v = tid >> 4, d4 = tid & 15;
    int b = d4 >> 3, f4 = d4 & 7;
    const float4* tin = (const float4*)(d_T + (size_t)1 * VV * 64);
    float4 acc = make_float4(0.f, 0.f, 0.f, 0.f);
#pragma unroll
    for (int j = 0; j < NNZ; ++j) {
        int c = __ldg(&cols[v * NNZ + j]);
        float w = __ldg(&vals[v * NNZ + j]);
        float4 t = __ldg(&tin[(size_t)c * 16 + d4]);
        acc.x += w * t.x; acc.y += w * t.y; acc.z += w * t.z; acc.w += w * t.w;
    }
    float4 p = __ldg(&((const float4*)x)[((size_t)b * VV + v) * 8 + f4]);
    acc.x = 2.f * acc.x - p.x; acc.y = 2.f * acc.y - p.y;
    acc.z = 2.f * acc.z - p.z; acc.w = 2.f * acc.w - p.w;
    ((float4*)(d_T + (size_t)2 * VV * 64))[tid] = acc;
}

// t[kout] = 2 L t[kin] - t[kp2]
__global__ void __launch_bounds__(256) k_spmm1_rest(int kin, int kp2, int kout,
                                                    const float* __restrict__ vals,
                                                    const int* __restrict__ cols) {
    int tid = blockIdx.x * 256 + threadIdx.x;
    int v = tid >> 4, d4 = tid & 15;
    const float4* tin = (const float4*)(d_T + (size_t)kin * VV * 64);
    float4 acc = make_float4(0.f, 0.f, 0.f, 0.f);
#pragma unroll
    for (int j = 0; j < NNZ; ++j) {
        int c = __ldg(&cols[v * NNZ + j]);
        float w = __ldg(&vals[v * NNZ + j]);
        float4 t = __ldg(&tin[(size_t)c * 16 + d4]);
        acc.x += w * t.x; acc.y += w * t.y; acc.z += w * t.z; acc.w += w * t.w;
    }
    float4 p = ((const float4*)(d_T + (size_t)kp2 * VV * 64))[tid];
    acc.x = 2.f * acc.x - p.x; acc.y = 2.f * acc.y - p.y;
    acc.z = 2.f * acc.z - p.z; acc.w = 2.f * acc.w - p.w;
    ((float4*)(d_T + (size_t)kout * VV * 64))[tid] = acc;
}

// ---------------- block2 SPMM family (D=128, 4 floats/thread) ----------------
// h~ = leaky(GN1(h1pre)); u1 = L h~   (h1pre raw in d_U[0])
__global__ void __launch_bounds__(256) k_spmm2_first(const float* __restrict__ gamma,
                                                     const float* __restrict__ beta,
                                                     const float* __restrict__ vals,
                                                     const int* __restrict__ cols) {
    int tid = blockIdx.x * 256 + threadIdx.x;
    int v = tid >> 5, d4 = tid & 31;
    int b = d4 >> 4, c0 = (d4 & 15) * 4;
    float4 scl, sft;
    gn1_params(b, c0, gamma, beta, scl, sft);
    const float4* tin = (const float4*)d_U;
    float4 acc = make_float4(0.f, 0.f, 0.f, 0.f);
#pragma unroll
    for (int j = 0; j < NNZ; ++j) {
        int c = __ldg(&cols[v * NNZ + j]);
        float w = __ldg(&vals[v * NNZ + j]);
        float4 t = __ldg(&tin[(size_t)c * 32 + d4]);
        t.x = lk(fmaf(t.x, scl.x, sft.x)); t.y = lk(fmaf(t.y, scl.y, sft.y));
        t.z = lk(fmaf(t.z, scl.z, sft.z)); t.w = lk(fmaf(t.w, scl.w, sft.w));
        acc.x += w * t.x; acc.y += w * t.y; acc.z += w * t.z; acc.w += w * t.w;
    }
    ((float4*)(d_U + (size_t)1 * VV * 128))[tid] = acc;
}

// u2 = 2 L u1 - h~
__global__ void __launch_bounds__(256) k_spmm2_second(const float* __restrict__ gamma,
                                                      const float* __restrict__ beta,
                                                      const float* __restrict__ vals,
                                                      const int* __restrict__ cols) {
    int tid = blockIdx.x * 256 + threadIdx.x;
    int v = tid >> 5, d4 = tid & 31;
    int b = d4 >> 4, c0 = (d4 & 15) * 4;
    float4 scl, sft;
    gn1_params(b, c0, gamma, beta, scl, sft);
    const float4* tin = (const float4*)(d_U + (size_t)1 * VV * 128);
    float4 acc = make_float4(0.f, 0.f, 0.f, 0.f);
#pragma unroll
    for (int j = 0; j < NNZ; ++j) {
        int c = __ldg(&cols[v * NNZ + j]);
        float w = __ldg(&vals[v * NNZ + j]);
        float4 t = __ldg(&tin[(size_t)c * 32 + d4]);
        acc.x += w * t.x; acc.y += w * t.y; acc.z += w * t.z; acc.w += w * t.w;
    }
    float4 p = ((const float4*)d_U)[tid];
    p.x = lk(fmaf(p.x, scl.x, sft.x)); p.y = lk(fmaf(p.y, scl.y, sft.y));
    p.z = lk(fmaf(p.z, scl.z, sft.z)); p.w = lk(fmaf(p.w, scl.w, sft.w));
    acc.x = 2.f * acc.x - p.x; acc.y = 2.f * acc.y - p.y;
    acc.z = 2.f * acc.z - p.z; acc.w = 2.f * acc.w - p.w;
    ((float4*)(d_U + (size_t)2 * VV * 128))[tid] = acc;
}

__global__ void __launch_bounds__(256) k_spmm2_rest(int kin, int kp2, int kout,
                                                    const float* __restrict__ vals,
                                                    const int* __restrict__ cols) {
    int tid = blockIdx.x * 256 + threadIdx.x;
    int v = tid >> 5, d4 = tid & 31;
    const float4* tin = (const float4*)(d_U + (size_t)kin * VV * 128);
    float4 acc = make_float4(0.f, 0.f, 0.f, 0.f);
#pragma unroll
    for (int j = 0; j < NNZ; ++j) {
        int c = __ldg(&cols[v * NNZ + j]);
        float w = __ldg(&vals[v * NNZ + j]);
        float4 t = __ldg(&tin[(size_t)c * 32 + d4]);
        acc.x += w * t.x; acc.y += w * t.y; acc.z += w * t.z; acc.w += w * t.w;
    }
    float4 p = ((const float4*)(d_U + (size_t)kp2 * VV * 128))[tid];
    acc.x = 2.f * acc.x - p.x; acc.y = 2.f * acc.y - p.y;
    acc.z = 2.f * acc.z - p.z; acc.w = 2.f * acc.w - p.w;
    ((float4*)(d_U + (size_t)kout * VV * 128))[tid] = acc;
}

// ---------------- GEMM 1: [98304 x 256] @ [256 x 128] (W1|Wr), fused GN1 stats ----------------
__global__ void __launch_bounds__(256) k_gemm1_mma(const float* __restrict__ x,
                                                   const float* __restrict__ b1,
                                                   const float* __restrict__ br) {
    __shared__ float As[128][36];
    __shared__ float Bs[128][36];
    int v0 = blockIdx.x * 64;
    int tid = threadIdx.x;
    int warp = tid >> 5, lane = tid & 31;
    int g = lane >> 2, t = lane & 3;
    int wm = warp >> 1, wn = warp & 1;  // 4 x 2 warps
    int m_w = wm * 32, n_w = wn * 64;

    float acc[2][8][4];
#pragma unroll
    for (int mi = 0; mi < 2; ++mi)
#pragma unroll
        for (int ni = 0; ni < 8; ++ni)
#pragma unroll
            for (int q = 0; q < 4; ++q) acc[mi][ni][q] = 0.f;

#pragma unroll 1
    for (int c = 0; c < 8; ++c) {
        if (c == 0) {
            // chunk 0: A = x directly (T0)
            const float4* xs = (const float4*)x;
#pragma unroll
            for (int tl = 0; tl < 4; ++tl) {
                int lt4 = tid + tl * 256;
                int voff = lt4 >> 4, bb = (lt4 >> 3) & 1, f4 = lt4 & 7;
                float4 val = xs[((size_t)bb * VV + v0 + voff) * 8 + f4];
                val.x = ftf32(val.x); val.y = ftf32(val.y);
                val.z = ftf32(val.z); val.w = ftf32(val.w);
                *(float4*)&As[voff * 2 + bb][f4 * 4] = val;
            }
        } else {
            const float4* asrc = (const float4*)(d_T + (size_t)c * VV * 64 + (size_t)v0 * 64);
#pragma unroll
            for (int tl = 0; tl < 4; ++tl) {
                int lt4 = tid + tl * 256;
                float4 val = asrc[lt4];
                val.x = ftf32(val.x); val.y = ftf32(val.y);
                val.z = ftf32(val.z); val.w = ftf32(val.w);
                int lt = lt4 * 4;
                int r = ((lt >> 6) << 1) | ((lt >> 5) & 1);
                *(float4*)&As[r][lt & 31] = val;
            }
        }
        const float4* bsrc = (const float4*)(d_Bt1 + c * 4096);
#pragma unroll
        for (int tl = 0; tl < 4; ++tl) {
            int lt4 = tid + tl * 256;
            float4 val = bsrc[lt4];
            int lt = lt4 * 4;
            *(float4*)&Bs[lt >> 5][lt & 31] = val;
        }
        __syncthreads();
#pragma unroll
        for (int ks = 0; ks < 4; ++ks) {
            int k0 = ks * 8;
            uint32_t a[2][4];
#pragma unroll
            for (int mi = 0; mi < 2; ++mi) {
                int m = m_w + mi * 16;
                a[mi][0] = __float_as_uint(As[m + g][k0 + t]);
                a[mi][1] = __float_as_uint(As[m + g + 8][k0 + t]);
                a[mi][2] = __float_as_uint(As[m + g][k0 + t + 4]);
                a[mi][3] = __float_as_uint(As[m + g + 8][k0 + t + 4]);
            }
#pragma unroll
            for (int ni = 0; ni < 8; ++ni) {
                int n = n_w + ni * 8;
                uint32_t b0 = __float_as_uint(Bs[n + g][k0 + t]);
                uint32_t b1v = __float_as_uint(Bs[n + g][k0 + t + 4]);
#pragma unroll
                for (int mi = 0; mi < 2; ++mi)
                    mma_tf32(acc[mi][ni], a[mi][0], a[mi][1], a[mi][2], a[mi][3], b0, b1v);
            }
        }
        __syncthreads();
    }
    // epilogue + fused GN1 stats (wn==0 warps only: cols 0..63)
    float sni[8], s2ni[8];
#pragma unroll
    for (int ni = 0; ni < 8; ++ni) { sni[ni] = 0.f; s2ni[ni] = 0.f; }
#pragma unroll
    for (int mi = 0; mi < 2; ++mi) {
        int r1 = m_w + mi * 16 + g;
        int v1 = v0 + (r1 >> 1), bb1 = r1 & 1;
        int r2 = r1 + 8;
        int v2 = v0 + (r2 >> 1), bb2 = r2 & 1;
#pragma unroll
        for (int ni = 0; ni < 8; ++ni) {
            int n = n_w + ni * 8 + t * 2;
            float2 p1 = make_float2(acc[mi][ni][0], acc[mi][ni][1]);
            float2 p2 = make_float2(acc[mi][ni][2], acc[mi][ni][3]);
            if (n < 64) {
                float bx = __ldg(&b1[n]), by = __ldg(&b1[n + 1]);
                p1.x += bx; p1.y += by; p2.x += bx; p2.y += by;
                *(float2*)(d_U + (size_t)v1 * 128 + bb1 * 64 + n) = p1;
                *(float2*)(d_U + (size_t)v2 * 128 + bb2 * 64 + n) = p2;
                sni[ni] += p1.x + p1.y + p2.x + p2.y;
                s2ni[ni] += p1.x * p1.x + p1.y * p1.y + p2.x * p2.x + p2.y * p2.y;
            } else {
                int o = n - 64;
                float bx = __ldg(&br[o]), by = __ldg(&br[o + 1]);
                p1.x += bx; p1.y += by; p2.x += bx; p2.y += by;
                *(float2*)(d_res + (size_t)bb1 * VV * 64 + (size_t)v1 * 64 + o) = p1;
                *(float2*)(d_res + (size_t)bb2 * VV * 64 + (size_t)v2 * 64 + o) = p2;
            }
        }
    }
    if (wn == 0) {
        // rows handled by this thread all share b = g&1; reduce over lane bits {0,1,3,4}
#pragma unroll
        for (int ni = 0; ni < 8; ++ni) {
            float s = sni[ni], s2 = s2ni[ni];
#pragma unroll
            for (int m = 1; m <= 16; m <<= 1) {
                if (m == 4) continue;
                s += __shfl_xor_sync(0xFFFFFFFFu, s, m);
                s2 += __shfl_xor_sync(0xFFFFFFFFu, s2, m);
            }
            if ((lane & 0x1B) == 0) {  // lanes 0 (b=0) and 4 (b=1)
                int bb = (lane >> 2) & 1;
                atomicAdd(&d_stats[(bb * 8 + ni) * 2], s);
                atomicAdd(&d_stats[(bb * 8 + ni) * 2 + 1], s2);
            }
        }
    }
}

// ---------------- GEMM 2: [98304 x 512] @ [512 x 64] (W2), GN1 on-the-fly, fused GN2 stats ----
__global__ void __launch_bounds__(256) k_gemm2_mma(const float* __restrict__ g1,
                                                   const float* __restrict__ be1,
                                                   const float* __restrict__ b2,
                                                   float* __restrict__ out) {
    __shared__ float As[128][36];
    __shared__ float Bs[64][36];
    int v0 = blockIdx.x * 64;
    int tid = threadIdx.x;
    int warp = tid >> 5, lane = tid & 31;
    int g = lane >> 2, t = lane & 3;
    int m_w = warp * 16;  // 8 warps along M

    float acc[8][4];
#pragma unroll
    for (int ni = 0; ni < 8; ++ni)
#pragma unroll
        for (int q = 0; q < 4; ++q) acc[ni][q] = 0.f;

#pragma unroll 1
    for (int c = 0; c < 16; ++c) {
        int kk = c >> 1, f0 = (c & 1) * 32;
        const float4* asrc = (const float4*)(d_U + (size_t)kk * VV * 128 + (size_t)v0 * 128 + f0);
#pragma unroll
        for (int tl = 0; tl < 4; ++tl) {
            int lt4 = tid + tl * 256;
            int r = lt4 >> 3, f4 = lt4 & 7;
            float4 val = asrc[(r >> 1) * 32 + (r & 1) * 16 + f4];
            if (kk == 0) {  // chunk 0/1: h1pre raw -> apply GN1 + leaky
                float4 scl, sft;
                gn1_params(r & 1, f0 + f4 * 4, g1, be1, scl, sft);
                val.x = lk(fmaf(val.x, scl.x, sft.x));
                val.y = lk(fmaf(val.y, scl.y, sft.y));
                val.z = lk(fmaf(val.z, scl.z, sft.z));
                val.w = lk(fmaf(val.w, scl.w, sft.w));
            }
            val.x = ftf32(val.x); val.y = ftf32(val.y);
            val.z = ftf32(val.z); val.w = ftf32(val.w);
            *(float4*)&As[r][f4 * 4] = val;
        }
        const float4* bsrc = (const float4*)(d_Bt2 + c * 2048);
#pragma unroll
        for (int tl = 0; tl < 2; ++tl) {
            int lt4 = tid + tl * 256;
            float4 val = bsrc[lt4];
            int lt = lt4 * 4;
            *(float4*)&Bs[lt >> 5][lt & 31] = val;
        }
        __syncthreads();
#pragma unroll
        for (int ks = 0; ks < 4; ++ks) {
            int k0 = ks * 8;
            uint32_t a0 = __float_as_uint(As[m_w + g][k0 + t]);
            uint32_t a1 = __float_as_uint(As[m_w + g + 8][k0 + t]);
            uint32_t a2 = __float_as_uint(As[m_w + g][k0 + t + 4]);
            uint32_t a3 = __float_as_uint(As[m_w + g + 8][k0 + t + 4]);
#pragma unroll
            for (int ni = 0; ni < 8; ++ni) {
                int n = ni * 8;
                uint32_t b0 = __float_as_uint(Bs[n + g][k0 + t]);
                uint32_t b1v = __float_as_uint(Bs[n + g][k0 + t + 4]);
                mma_tf32(acc[ni], a0, a1, a2, a3, b0, b1v);
            }
        }
        __syncthreads();
    }
    int r1 = m_w + g;
    int v1 = v0 + (r1 >> 1), bb1 = r1 & 1;
    int r2 = r1 + 8;
    int v2 = v0 + (r2 >> 1), bb2 = r2 & 1;
    float* o1 = out + (size_t)bb1 * VV * 64 + (size_t)v1 * 64;
    float* o2 = out + (size_t)bb2 * VV * 64 + (size_t)v2 * 64;
#pragma unroll
    for (int ni = 0; ni < 8; ++ni) {
        int n = ni * 8 + t * 2;
        float bx = __ldg(&b2[n]), by = __ldg(&b2[n + 1]);
        float e0 = acc[ni][0] + bx, e1 = acc[ni][1] + by;
        float e2 = acc[ni][2] + bx, e3 = acc[ni][3] + by;
        *(float2*)(o1 + n) = make_float2(e0, e1);
        *(float2*)(o2 + n) = make_float2(e2, e3);
        // fused GN2 stats (b = g&1 for both rows)
        float s = e0 + e1 + e2 + e3;
        float s2 = e0 * e0 + e1 * e1 + e2 * e2 + e3 * e3;
#pragma unroll
        for (int m = 1; m <= 16; m <<= 1) {
            if (m == 4) continue;
            s += __shfl_xor_sync(0xFFFFFFFFu, s, m);
            s2 += __shfl_xor_sync(0xFFFFFFFFu, s2, m);
        }
        if ((lane & 0x1B) == 0) {
            int bb = (lane >> 2) & 1;
            atomicAdd(&d_stats[32 + (bb * 8 + ni) * 2], s);
            atomicAdd(&d_stats[32 + (bb * 8 + ni) * 2 + 1], s2);
        }
    }
}

// ---------------- final: out = leaky(GN2(h2pre)) + res, in place ----------------
__global__ void k_final(float* __restrict__ out,
                        const float* __restrict__ gamma, const float* __restrict__ beta) {
    int idx = blockIdx.x * blockDim.x + threadIdx.x;
    if (idx >= 2 * VV * 64) return;
    int b = idx / (VV * 64);
    int c = idx & 63, g = c >> 3;
    int bin = 32 + (b * 8 + g) * 2;
    float mu = d_stats[bin] / GN_N;
    float var = d_stats[bin + 1] / GN_N - mu * mu;
    float rstd = rsqrtf(var + 1e-5f);
    float y = (out[idx] - mu) * rstd * gamma[c] + beta[c];
    out[idx] = fmaxf(y, 0.1f * y) + d_res[idx];
}

// ---------------- launch ----------------
extern "C" void kernel_launch(void* const* d_in, const int* in_sizes, int n_in,
                              void* d_out, int out_size) {
    const float* x    = (const float*)d_in[0];
    const float* vals = (const float*)d_in[1];
    const int*   cols = (const int*)d_in[3];
    const float* W1 = (const float*)d_in[4];
    const float* b1 = (const float*)d_in[5];
    const float* g1 = (const float*)d_in[6];
    const float* be1 = (const float*)d_in[7];
    const float* W2 = (const float*)d_in[8];
    const float* b2 = (const float*)d_in[9];
    const float* g2 = (const float*)d_in[10];
    const float* be2 = (const float*)d_in[11];
    const float* Wr = (const float*)d_in[12];
    const float* br = (const float*)d_in[13];
    float* out = (float*)d_out;

    k_zero_stats<<<1, 64>>>();
    k_wtrans<<<(8 * 128 * 32 + 16 * 64 * 32) / 256, 256>>>(W1, Wr, W2);

    // block1 Chebyshev terms t1..t7 (t0 = x read in place)
    const int g64 = (VV * 16) / 256;
    k_spmm1_first<<<g64, 256>>>(x, vals, cols);
    k_spmm1_second<<<g64, 256>>>(x, vals, cols);
    k_spmm1_rest<<<g64, 256>>>(2, 1, 3, vals, cols);
    k_spmm1_rest<<<g64, 256>>>(3, 2, 4, vals, cols);
    k_spmm1_rest<<<g64, 256>>>(4, 3, 5, vals, cols);
    k_spmm1_rest<<<g64, 256>>>(5, 4, 6, vals, cols);
    k_spmm1_rest<<<g64, 256>>>(6, 5, 7, vals, cols);

    // h1pre (raw, into d_U[0]) + residual + fused GN1 stats
    k_gemm1_mma<<<VV / 64, 256>>>(x, b1, br);

    // block2 Chebyshev terms u1..u7 (u0 = GN1+leaky(h1pre) applied on the fly)
    const int g128 = (VV * 32) / 256;
    k_spmm2_first<<<g128, 256>>>(g1, be1, vals, cols);
    k_spmm2_second<<<g128, 256>>>(g1, be1, vals, cols);
    k_spmm2_rest<<<g128, 256>>>(2, 1, 3, vals, cols);
    k_spmm2_rest<<<g128, 256>>>(3, 2, 4, vals, cols);
    k_spmm2_rest<<<g128, 256>>>(4, 3, 5, vals, cols);
    k_spmm2_rest<<<g128, 256>>>(5, 4, 6, vals, cols);
    k_spmm2_rest<<<g128, 256>>>(6, 5, 7, vals, cols);

    // h2pre -> out + fused GN2 stats (GN1 applied on the fly to chunks 0/1)
    k_gemm2_mma<<<VV / 64, 256>>>(g1, be1, b2, out);

    // final: GN2 + LeakyReLU + residual add
    k_final<<<(2 * VV * 64) / 256, 256>>>(out, g2, be2);
}

// round 8
// speedup vs baseline: 1.3482x; 1.3482x over previous
#include <cuda_runtime.h>
#include <cstdint>

#define VV 49152
#define NNZ 9
#define GN_N 393216.0f  // V * (C/G)

// ---------------- scratch (device globals; no runtime allocation) ----------------
__device__ float d_T[(size_t)8 * VV * 64];    // block1 Chebyshev terms 1..7 (slot 0 unused; t0 = x)
__device__ float d_U[(size_t)8 * VV * 128];   // slot0 = h1 (normalized in place), 1..7 = block2 terms
__device__ float d_res[(size_t)2 * VV * 64];  // residual conv output [b][v][o]
__device__ float d_stats[64];                 // [0:32) GN1 (sum,sumsq)x16, [32:64) GN2
__device__ float d_Bt1[8 * 128 * 32];         // GEMM1 B^T (W1|Wr), tf32-rounded
__device__ float d_Bt2[16 * 64 * 32];         // GEMM2 B^T (W2), tf32-rounded

// ---------------- helpers ----------------
__device__ __forceinline__ float ftf32(float x) {
    uint32_t r;
    asm("cvt.rna.tf32.f32 %0, %1;" : "=r"(r) : "f"(x));
    return __uint_as_float(r);
}
__device__ __forceinline__ void mma_tf32(float* d, uint32_t a0, uint32_t a1, uint32_t a2,
                                         uint32_t a3, uint32_t b0, uint32_t b1) {
    asm volatile(
        "mma.sync.aligned.m16n8k8.row.col.f32.tf32.tf32.f32 "
        "{%0,%1,%2,%3}, {%4,%5,%6,%7}, {%8,%9}, {%0,%1,%2,%3};"
        : "+f"(d[0]), "+f"(d[1]), "+f"(d[2]), "+f"(d[3])
        : "r"(a0), "r"(a1), "r"(a2), "r"(a3), "r"(b0), "r"(b1));
}

// ---------------- small kernels ----------------
__global__ void k_zero_stats() {
    if (threadIdx.x < 64) d_stats[threadIdx.x] = 0.0f;
}

// Pre-transpose weights into [o][k] layout, tf32-rounded.
__global__ void k_wtrans(const float* __restrict__ W1, const float* __restrict__ Wr,
                         const float* __restrict__ W2) {
    int idx = blockIdx.x * blockDim.x + threadIdx.x;
    if (idx < 8 * 128 * 32) {
        int kk = idx >> 12, r = idx & 4095, o = r >> 5, f = r & 31;
        float w = (o < 64) ? W1[kk * 2048 + f * 64 + o] : Wr[kk * 2048 + f * 64 + (o - 64)];
        d_Bt1[idx] = ftf32(w);
    } else if (idx < 8 * 128 * 32 + 16 * 64 * 32) {
        int j = idx - 8 * 128 * 32;
        int c = j >> 11, rr = j & 2047, o = rr >> 5, f = rr & 31;
        int kk = c >> 1, f0 = (c & 1) * 32;
        d_Bt2[j] = ftf32(W2[kk * 4096 + (f0 + f) * 64 + o]);
    }
}

// ---------------- block1 SPMM family (D=64, 4 floats/thread) ----------------
// t1 = L x  (gather straight from x; x layout [b][v][32])
__global__ void __launch_bounds__(256) k_spmm1_first(const float* __restrict__ x,
                                                     const float* __restrict__ vals,
                                                     const int* __restrict__ cols) {
    int tid = blockIdx.x * 256 + threadIdx.x;
    int v = tid >> 4, d4 = tid & 15;
    int b = d4 >> 3, f4 = d4 & 7;
    const float4* xs = (const float4*)x;
    size_t xbase = (size_t)b * VV * 8 + f4;
    float4 acc = make_float4(0.f, 0.f, 0.f, 0.f);
#pragma unroll
    for (int j = 0; j < NNZ; ++j) {
        int c = __ldg(&cols[v * NNZ + j]);
        float w = __ldg(&vals[v * NNZ + j]);
        float4 t = __ldg(&xs[xbase + (size_t)c * 8]);
        acc.x += w * t.x; acc.y += w * t.y; acc.z += w * t.z; acc.w += w * t.w;
    }
    ((float4*)(d_T + (size_t)1 * VV * 64))[tid] = acc;
}

// t2 = 2 L t1 - x
__global__ void __launch_bounds__(256) k_spmm1_second(const float* __restrict__ x,
                                                      const float* __restrict__ vals,
                                                      const int* __restrict__ cols) {
    int tid = blockIdx.x * 256 + threadIdx.x;
    int v = tid >> 4, d4 = tid & 15;
    int b = d4 >> 3, f4 = d4 & 7;
    const float4* tin = (const float4*)(d_T + (size_t)1 * VV * 64);
    float4 acc = make_float4(0.f, 0.f, 0.f, 0.f);
#pragma unroll
    for (int j = 0; j < NNZ; ++j) {
        int c = __ldg(&cols[v * NNZ + j]);
        float w = __ldg(&vals[v * NNZ + j]);
        float4 t = __ldg(&tin[(size_t)c * 16 + d4]);
        acc.x += w * t.x; acc.y += w * t.y; acc.z += w * t.z; acc.w += w * t.w;
    }
    float4 p = __ldg(&((const float4*)x)[((size_t)b * VV + v) * 8 + f4]);
    acc.x = 2.f * acc.x - p.x; acc.y = 2.f * acc.y - p.y;
    acc.z = 2.f * acc.z - p.z; acc.w = 2.f * acc.w - p.w;
    ((float4*)(d_T + (size_t)2 * VV * 64))[tid] = acc;
}

// t[kout] = 2 L t[kin] - t[kp2]
__global__ void __launch_bounds__(256) k_spmm1_rest(int kin, int kp2, int kout,
                                                    const float* __restrict__ vals,
                                                    const int* __restrict__ cols) {
    int tid = blockIdx.x * 256 + threadIdx.x;
    int v = tid >> 4, d4 = tid & 15;
    const float4* tin = (const float4*)(d_T + (size_t)kin * VV * 64);
    float4 acc = make_float4(0.f, 0.f, 0.f, 0.f);
#pragma unroll
    for (int j = 0; j < NNZ; ++j) {
        int c = __ldg(&cols[v * NNZ + j]);
        float w = __ldg(&vals[v * NNZ + j]);
        float4 t = __ldg(&tin[(size_t)c * 16 + d4]);
        acc.x += w * t.x; acc.y += w * t.y; acc.z += w * t.z; acc.w += w * t.w;
    }
    float4 p = ((const float4*)(d_T + (size_t)kp2 * VV * 64))[tid];
    acc.x = 2.f * acc.x - p.x; acc.y = 2.f * acc.y - p.y;
    acc.z = 2.f * acc.z - p.z; acc.w = 2.f * acc.w - p.w;
    ((float4*)(d_T + (size_t)kout * VV * 64))[tid] = acc;
}

// ---------------- block2 SPMM family (D=128, 4 floats/thread, plain) ----------------
// u[kout] = L u[kin]            (FIRST)
// u[kout] = 2 L u[kin] - u[kp2] (otherwise)
template <bool FIRST>
__global__ void __launch_bounds__(256) k_spmm2(int kin, int kp2, int kout,
                                               const float* __restrict__ vals,
                                               const int* __restrict__ cols) {
    int tid = blockIdx.x * 256 + threadIdx.x;
    int v = tid >> 5, d4 = tid & 31;
    const float4* tin = (const float4*)(d_U + (size_t)kin * VV * 128);
    float4 acc = make_float4(0.f, 0.f, 0.f, 0.f);
#pragma unroll
    for (int j = 0; j < NNZ; ++j) {
        int c = __ldg(&cols[v * NNZ + j]);
        float w = __ldg(&vals[v * NNZ + j]);
        float4 t = __ldg(&tin[(size_t)c * 32 + d4]);
        acc.x += w * t.x; acc.y += w * t.y; acc.z += w * t.z; acc.w += w * t.w;
    }
    if (!FIRST) {
        float4 p = ((const float4*)(d_U + (size_t)kp2 * VV * 128))[tid];
        acc.x = 2.f * acc.x - p.x; acc.y = 2.f * acc.y - p.y;
        acc.z = 2.f * acc.z - p.z; acc.w = 2.f * acc.w - p.w;
    }
    ((float4*)(d_U + (size_t)kout * VV * 128))[tid] = acc;
}

// ---------------- GEMM 1: [98304 x 256] @ [256 x 128] (W1|Wr) ----------------
// Row r = 2*v + b. Chunk 0 = x directly; chunks 1..7 = d_T. Cols 0..63 -> d_U(+b1); 64..127 -> d_res(+br).
__global__ void __launch_bounds__(256) k_gemm1_mma(const float* __restrict__ x,
                                                   const float* __restrict__ b1,
                                                   const float* __restrict__ br) {
    __shared__ float As[128][36];
    __shared__ float Bs[128][36];
    int v0 = blockIdx.x * 64;
    int tid = threadIdx.x;
    int warp = tid >> 5, lane = tid & 31;
    int g = lane >> 2, t = lane & 3;
    int wm = warp >> 1, wn = warp & 1;  // 4 x 2 warps
    int m_w = wm * 32, n_w = wn * 64;

    float acc[2][8][4];
#pragma unroll
    for (int mi = 0; mi < 2; ++mi)
#pragma unroll
        for (int ni = 0; ni < 8; ++ni)
#pragma unroll
            for (int q = 0; q < 4; ++q) acc[mi][ni][q] = 0.f;

#pragma unroll 1
    for (int c = 0; c < 8; ++c) {
        if (c == 0) {
            const float4* xs = (const float4*)x;
#pragma unroll
            for (int tl = 0; tl < 4; ++tl) {
                int lt4 = tid + tl * 256;
                int voff = lt4 >> 4, bb = (lt4 >> 3) & 1, f4 = lt4 & 7;
                float4 val = xs[((size_t)bb * VV + v0 + voff) * 8 + f4];
                val.x = ftf32(val.x); val.y = ftf32(val.y);
                val.z = ftf32(val.z); val.w = ftf32(val.w);
                *(float4*)&As[voff * 2 + bb][f4 * 4] = val;
            }
        } else {
            const float4* asrc = (const float4*)(d_T + (size_t)c * VV * 64 + (size_t)v0 * 64);
#pragma unroll
            for (int tl = 0; tl < 4; ++tl) {
                int lt4 = tid + tl * 256;
                float4 val = asrc[lt4];
                val.x = ftf32(val.x); val.y = ftf32(val.y);
                val.z = ftf32(val.z); val.w = ftf32(val.w);
                int lt = lt4 * 4;
                int r = ((lt >> 6) << 1) | ((lt >> 5) & 1);
                *(float4*)&As[r][lt & 31] = val;
            }
        }
        const float4* bsrc = (const float4*)(d_Bt1 + c * 4096);
#pragma unroll
        for (int tl = 0; tl < 4; ++tl) {
            int lt4 = tid + tl * 256;
            float4 val = bsrc[lt4];
            int lt = lt4 * 4;
            *(float4*)&Bs[lt >> 5][lt & 31] = val;
        }
        __syncthreads();
#pragma unroll
        for (int ks = 0; ks < 4; ++ks) {
            int k0 = ks * 8;
            uint32_t a[2][4];
#pragma unroll
            for (int mi = 0; mi < 2; ++mi) {
                int m = m_w + mi * 16;
                a[mi][0] = __float_as_uint(As[m + g][k0 + t]);
                a[mi][1] = __float_as_uint(As[m + g + 8][k0 + t]);
                a[mi][2] = __float_as_uint(As[m + g][k0 + t + 4]);
                a[mi][3] = __float_as_uint(As[m + g + 8][k0 + t + 4]);
            }
#pragma unroll
            for (int ni = 0; ni < 8; ++ni) {
                int n = n_w + ni * 8;
                uint32_t b0 = __float_as_uint(Bs[n + g][k0 + t]);
                uint32_t b1v = __float_as_uint(Bs[n + g][k0 + t + 4]);
#pragma unroll
                for (int mi = 0; mi < 2; ++mi)
                    mma_tf32(acc[mi][ni], a[mi][0], a[mi][1], a[mi][2], a[mi][3], b0, b1v);
            }
        }
        __syncthreads();
    }
#pragma unroll
    for (int mi = 0; mi < 2; ++mi) {
        int r1 = m_w + mi * 16 + g;
        int v1 = v0 + (r1 >> 1), bb1 = r1 & 1;
        int r2 = r1 + 8;
        int v2 = v0 + (r2 >> 1), bb2 = r2 & 1;
#pragma unroll
        for (int ni = 0; ni < 8; ++ni) {
            int n = n_w + ni * 8 + t * 2;
            float2 p1 = make_float2(acc[mi][ni][0], acc[mi][ni][1]);
            float2 p2 = make_float2(acc[mi][ni][2], acc[mi][ni][3]);
            if (n < 64) {
                float bx = __ldg(&b1[n]), by = __ldg(&b1[n + 1]);
                p1.x += bx; p1.y += by; p2.x += bx; p2.y += by;
                *(float2*)(d_U + (size_t)v1 * 128 + bb1 * 64 + n) = p1;
                *(float2*)(d_U + (size_t)v2 * 128 + bb2 * 64 + n) = p2;
            } else {
                int o = n - 64;
                float bx = __ldg(&br[o]), by = __ldg(&br[o + 1]);
                p1.x += bx; p1.y += by; p2.x += bx; p2.y += by;
                *(float2*)(d_res + (size_t)bb1 * VV * 64 + (size_t)v1 * 64 + o) = p1;
                *(float2*)(d_res + (size_t)bb2 * VV * 64 + (size_t)v2 * 64 + o) = p2;
            }
        }
    }
}

// ---------------- GEMM 2: [98304 x 512] @ [512 x 64] (W2) ----------------
__global__ void __launch_bounds__(256) k_gemm2_mma(const float* __restrict__ b2,
                                                   float* __restrict__ out) {
    __shared__ float As[128][36];
    __shared__ float Bs[64][36];
    int v0 = blockIdx.x * 64;
    int tid = threadIdx.x;
    int warp = tid >> 5, lane = tid & 31;
    int g = lane >> 2, t = lane & 3;
    int m_w = warp * 16;  // 8 warps along M

    float acc[8][4];
#pragma unroll
    for (int ni = 0; ni < 8; ++ni)
#pragma unroll
        for (int q = 0; q < 4; ++q) acc[ni][q] = 0.f;

#pragma unroll 1
    for (int c = 0; c < 16; ++c) {
        int kk = c >> 1, f0 = (c & 1) * 32;
        const float4* asrc = (const float4*)(d_U + (size_t)kk * VV * 128 + (size_t)v0 * 128 + f0);
#pragma unroll
        for (int tl = 0; tl < 4; ++tl) {
            int lt4 = tid + tl * 256;
            int r = lt4 >> 3, f4 = lt4 & 7;
            float4 val = asrc[(r >> 1) * 32 + (r & 1) * 16 + f4];
            val.x = ftf32(val.x); val.y = ftf32(val.y);
            val.z = ftf32(val.z); val.w = ftf32(val.w);
            *(float4*)&As[r][f4 * 4] = val;
        }
        const float4* bsrc = (const float4*)(d_Bt2 + c * 2048);
#pragma unroll
        for (int tl = 0; tl < 2; ++tl) {
            int lt4 = tid + tl * 256;
            float4 val = bsrc[lt4];
            int lt = lt4 * 4;
            *(float4*)&Bs[lt >> 5][lt & 31] = val;
        }
        __syncthreads();
#pragma unroll
        for (int ks = 0; ks < 4; ++ks) {
            int k0 = ks * 8;
            uint32_t a0 = __float_as_uint(As[m_w + g][k0 + t]);
            uint32_t a1 = __float_as_uint(As[m_w + g + 8][k0 + t]);
            uint32_t a2 = __float_as_uint(As[m_w + g][k0 + t + 4]);
            uint32_t a3 = __float_as_uint(As[m_w + g + 8][k0 + t + 4]);
#pragma unroll
            for (int ni = 0; ni < 8; ++ni) {
                int n = ni * 8;
                uint32_t b0 = __float_as_uint(Bs[n + g][k0 + t]);
                uint32_t b1v = __float_as_uint(Bs[n + g][k0 + t + 4]);
                mma_tf32(acc[ni], a0, a1, a2, a3, b0, b1v);
            }
        }
        __syncthreads();
    }
    int r1 = m_w + g;
    int v1 = v0 + (r1 >> 1), bb1 = r1 & 1;
    int r2 = r1 + 8;
    int v2 = v0 + (r2 >> 1), bb2 = r2 & 1;
    float* o1 = out + (size_t)bb1 * VV * 64 + (size_t)v1 * 64;
    float* o2 = out + (size_t)bb2 * VV * 64 + (size_t)v2 * 64;
#pragma unroll
    for (int ni = 0; ni < 8; ++ni) {
        int n = ni * 8 + t * 2;
        float bx = __ldg(&b2[n]), by = __ldg(&b2[n + 1]);
        *(float2*)(o1 + n) = make_float2(acc[ni][0] + bx, acc[ni][1] + by);
        *(float2*)(o2 + n) = make_float2(acc[ni][2] + bx, acc[ni][3] + by);
    }
}

// ---------------- GroupNorm stats ----------------
__global__ void k_stats1() {
    int tid = threadIdx.x;
    int c = tid & 63, b = (tid >> 6) & 1, seg = tid >> 7;
    int v0 = blockIdx.x * 384;
    float s = 0.f, s2 = 0.f;
    for (int v = v0 + seg; v < v0 + 384; v += 2) {
        float x = d_U[(size_t)v * 128 + b * 64 + c];
        s += x; s2 += x * x;
    }
    __shared__ float sm[256], sm2[256];
    sm[tid] = s; sm2[tid] = s2;
    __syncthreads();
    if (tid < 16) {
        int bb = tid >> 3, g = tid & 7;
        float ts = 0.f, ts2 = 0.f;
        for (int seg2 = 0; seg2 < 2; ++seg2)
            for (int cc = 0; cc < 8; ++cc) {
                int t = seg2 * 128 + bb * 64 + g * 8 + cc;
                ts += sm[t]; ts2 += sm2[t];
            }
        atomicAdd(&d_stats[(bb * 8 + g) * 2], ts);
        atomicAdd(&d_stats[(bb * 8 + g) * 2 + 1], ts2);
    }
}

__global__ void k_stats2(const float* __restrict__ H) {
    int tid = threadIdx.x;
    int c = tid & 63, sub = tid >> 6;
    int b = blockIdx.x & 1;
    int v0 = (blockIdx.x >> 1) * 768;
    const float* Hb = H + (size_t)b * VV * 64;
    float s = 0.f, s2 = 0.f;
    for (int v = v0 + sub; v < v0 + 768; v += 4) {
        float x = Hb[(size_t)v * 64 + c];
        s += x; s2 += x * x;
    }
    __shared__ float sm[256], sm2[256];
    sm[tid] = s; sm2[tid] = s2;
    __syncthreads();
    if (tid < 8) {
        int g = tid;
        float ts = 0.f, ts2 = 0.f;
        for (int sub2 = 0; sub2 < 4; ++sub2)
            for (int cc = 0; cc < 8; ++cc) {
                int t = sub2 * 64 + g * 8 + cc;
                ts += sm[t]; ts2 += sm2[t];
            }
        atomicAdd(&d_stats[32 + (b * 8 + g) * 2], ts);
        atomicAdd(&d_stats[32 + (b * 8 + g) * 2 + 1], ts2);
    }
}

// ---------------- GN apply + LeakyReLU ----------------
__global__ void k_gnapply1(const float* __restrict__ gamma, const float* __restrict__ beta) {
    int idx = blockIdx.x * blockDim.x + threadIdx.x;
    if (idx >= VV * 128) return;
    int rem = idx & 127, b = rem >> 6, c = rem & 63, g = c >> 3;
    int bin = (b * 8 + g) * 2;
    float mu = d_stats[bin] / GN_N;
    float var = d_stats[bin + 1] / GN_N - mu * mu;
    float rstd = rsqrtf(var + 1e-5f);
    float y = (d_U[idx] - mu) * rstd * gamma[c] + beta[c];
    d_U[idx] = fmaxf(y, 0.1f * y);
}

__global__ void k_final(float* __restrict__ out,
                        const float* __restrict__ gamma, const float* __restrict__ beta) {
    int idx = blockIdx.x * blockDim.x + threadIdx.x;
    if (idx >= 2 * VV * 64) return;
    int b = idx / (VV * 64);
    int c = idx & 63, g = c >> 3;
    int bin = 32 + (b * 8 + g) * 2;
    float mu = d_stats[bin] / GN_N;
    float var = d_stats[bin + 1] / GN_N - mu * mu;
    float rstd = rsqrtf(var + 1e-5f);
    float y = (out[idx] - mu) * rstd * gamma[c] + beta[c];
    out[idx] = fmaxf(y, 0.1f * y) + d_res[idx];
}

// ---------------- launch ----------------
extern "C" void kernel_launch(void* const* d_in, const int* in_sizes, int n_in,
                              void* d_out, int out_size) {
    const float* x    = (const float*)d_in[0];
    const float* vals = (const float*)d_in[1];
    const int*   cols = (const int*)d_in[3];
    const float* W1 = (const float*)d_in[4];
    const float* b1 = (const float*)d_in[5];
    const float* g1 = (const float*)d_in[6];
    const float* be1 = (const float*)d_in[7];
    const float* W2 = (const float*)d_in[8];
    const float* b2 = (const float*)d_in[9];
    const float* g2 = (const float*)d_in[10];
    const float* be2 = (const float*)d_in[11];
    const float* Wr = (const float*)d_in[12];
    const float* br = (const float*)d_in[13];
    float* out = (float*)d_out;

    k_zero_stats<<<1, 64>>>();
    k_wtrans<<<(8 * 128 * 32 + 16 * 64 * 32) / 256, 256>>>(W1, Wr, W2);

    // block1 Chebyshev terms t1..t7 (t0 = x read in place)
    const int g64 = (VV * 16) / 256;
    k_spmm1_first<<<g64, 256>>>(x, vals, cols);
    k_spmm1_second<<<g64, 256>>>(x, vals, cols);
    k_spmm1_rest<<<g64, 256>>>(2, 1, 3, vals, cols);
    k_spmm1_rest<<<g64, 256>>>(3, 2, 4, vals, cols);
    k_spmm1_rest<<<g64, 256>>>(4, 3, 5, vals, cols);
    k_spmm1_rest<<<g64, 256>>>(5, 4, 6, vals, cols);
    k_spmm1_rest<<<g64, 256>>>(6, 5, 7, vals, cols);

    // h1pre (raw, into d_U[0]) + residual
    k_gemm1_mma<<<VV / 64, 256>>>(x, b1, br);

    // GN1 stats + apply (in place -> d_U[0] becomes normalized h1)
    k_stats1<<<128, 256>>>();
    k_gnapply1<<<(VV * 128) / 256, 256>>>(g1, be1);

    // block2 Chebyshev terms u1..u7 (u0 = d_U[0])
    const int g128 = (VV * 32) / 256;
    k_spmm2<true><<<g128, 256>>>(0, 0, 1, vals, cols);
    k_spmm2<false><<<g128, 256>>>(1, 0, 2, vals, cols);
    k_spmm2<false><<<g128, 256>>>(2, 1, 3, vals, cols);
    k_spmm2<false><<<g128, 256>>>(3, 2, 4, vals, cols);
    k_spmm2<false><<<g128, 256>>>(4, 3, 5, vals, cols);
    k_spmm2<false><<<g128, 256>>>(5, 4, 6, vals, cols);
    k_spmm2<false><<<g128, 256>>>(6, 5, 7, vals, cols);

    // h2pre -> out
    k_gemm2_mma<<<VV / 64, 256>>>(b2, out);

    // GN2 + LeakyReLU + residual add
    k_stats2<<<128, 256>>>(out);
    k_final<<<(2 * VV * 64) / 256, 256>>>(out, g2, be2);
}

// round 9
// speedup vs baseline: 1.4744x; 1.0936x over previous
#include <cuda_runtime.h>
#include <cstdint>

#define VV 49152
#define NNZ 9
#define GN_N 393216.0f  // V * (C/G)

// ---------------- scratch (device globals; no runtime allocation) ----------------
__device__ float d_T[(size_t)8 * VV * 64];    // block1 Chebyshev terms 1..7 (t0 = x)
__device__ float d_U[(size_t)8 * VV * 128];   // slot0 = h1 (normalized in place), 1..7 = block2 terms
__device__ float d_res[(size_t)2 * VV * 64];  // residual conv output [b][v][o]
__device__ float d_stats[8 * 64];             // 8 spread buffers x [0:32) GN1, [32:64) GN2 (sum,sumsq)x16
__device__ float d_Bt1[8 * 128 * 32];         // GEMM1 B^T (W1|Wr), tf32-rounded
__device__ float d_Bt2[16 * 64 * 32];         // GEMM2 B^T (W2), tf32-rounded

// ---------------- helpers ----------------
__device__ __forceinline__ float ftf32(float x) {
    uint32_t r;
    asm("cvt.rna.tf32.f32 %0, %1;" : "=r"(r) : "f"(x));
    return __uint_as_float(r);
}
__device__ __forceinline__ uint32_t u_tf32(float x) {
    uint32_t r;
    asm("cvt.rna.tf32.f32 %0, %1;" : "=r"(r) : "f"(x));
    return r;
}
__device__ __forceinline__ void mma_tf32(float* d, uint32_t a0, uint32_t a1, uint32_t a2,
                                         uint32_t a3, uint32_t b0, uint32_t b1) {
    asm volatile(
        "mma.sync.aligned.m16n8k8.row.col.f32.tf32.tf32.f32 "
        "{%0,%1,%2,%3}, {%4,%5,%6,%7}, {%8,%9}, {%0,%1,%2,%3};"
        : "+f"(d[0]), "+f"(d[1]), "+f"(d[2]), "+f"(d[3])
        : "r"(a0), "r"(a1), "r"(a2), "r"(a3), "r"(b0), "r"(b1));
}
__device__ __forceinline__ void cpasync16(void* sptr, const void* gptr) {
    uint32_t sa = (uint32_t)__cvta_generic_to_shared(sptr);
    asm volatile("cp.async.cg.shared.global [%0], [%1], 16;" :: "r"(sa), "l"(gptr));
}
#define CP_COMMIT() asm volatile("cp.async.commit_group;" ::: "memory")
#define CP_WAIT(n)  asm volatile("cp.async.wait_group %0;" :: "n"(n) : "memory")

// warp-reduce (sum) over lane bits {0,1,3,4}; leaders = lanes 0 (b=0) and 4 (b=1)
__device__ __forceinline__ void red_stats(float& s, float& s2) {
#pragma unroll
    for (int m = 1; m <= 16; m <<= 1) {
        if (m == 4) continue;
        s += __shfl_xor_sync(0xFFFFFFFFu, s, m);
        s2 += __shfl_xor_sync(0xFFFFFFFFu, s2, m);
    }
}

// ---------------- weight transpose (+ stats zeroing) ----------------
__global__ void k_wtrans(const float* __restrict__ W1, const float* __restrict__ Wr,
                         const float* __restrict__ W2) {
    int idx = blockIdx.x * blockDim.x + threadIdx.x;
    if (idx < 8 * 64) d_stats[idx] = 0.0f;
    if (idx < 8 * 128 * 32) {
        int kk = idx >> 12, r = idx & 4095, o = r >> 5, f = r & 31;
        float w = (o < 64) ? W1[kk * 2048 + f * 64 + o] : Wr[kk * 2048 + f * 64 + (o - 64)];
        d_Bt1[idx] = ftf32(w);
    } else if (idx < 8 * 128 * 32 + 16 * 64 * 32) {
        int j = idx - 8 * 128 * 32;
        int c = j >> 11, rr = j & 2047, o = rr >> 5, f = rr & 31;
        int kk = c >> 1, f0 = (c & 1) * 32;
        d_Bt2[j] = ftf32(W2[kk * 4096 + (f0 + f) * 64 + o]);
    }
}

// ---------------- block1 SPMM family (D=64, 4 floats/thread) ----------------
__global__ void __launch_bounds__(256) k_spmm1_first(const float* __restrict__ x,
                                                     const float* __restrict__ vals,
                                                     const int* __restrict__ cols) {
    int tid = blockIdx.x * 256 + threadIdx.x;
    int v = tid >> 4, d4 = tid & 15;
    int b = d4 >> 3, f4 = d4 & 7;
    const float4* xs = (const float4*)x;
    size_t xbase = (size_t)b * VV * 8 + f4;
    float4 acc = make_float4(0.f, 0.f, 0.f, 0.f);
#pragma unroll
    for (int j = 0; j < NNZ; ++j) {
        int c = __ldg(&cols[v * NNZ + j]);
        float w = __ldg(&vals[v * NNZ + j]);
        float4 t = __ldg(&xs[xbase + (size_t)c * 8]);
        acc.x += w * t.x; acc.y += w * t.y; acc.z += w * t.z; acc.w += w * t.w;
    }
    ((float4*)(d_T + (size_t)1 * VV * 64))[tid] = acc;
}

__global__ void __launch_bounds__(256) k_spmm1_second(const float* __restrict__ x,
                                                      const float* __restrict__ vals,
                                                      const int* __restrict__ cols) {
    int tid = blockIdx.x * 256 + threadIdx.x;
    int v = tid >> 4, d4 = tid & 15;
    int b = d4 >> 3, f4 = d4 & 7;
    const float4* tin = (const float4*)(d_T + (size_t)1 * VV * 64);
    float4 acc = make_float4(0.f, 0.f, 0.f, 0.f);
#pragma unroll
    for (int j = 0; j < NNZ; ++j) {
        int c = __ldg(&cols[v * NNZ + j]);
        float w = __ldg(&vals[v * NNZ + j]);
        float4 t = __ldg(&tin[(size_t)c * 16 + d4]);
        acc.x += w * t.x; acc.y += w * t.y; acc.z += w * t.z; acc.w += w * t.w;
    }
    float4 p = __ldg(&((const float4*)x)[((size_t)b * VV + v) * 8 + f4]);
    acc.x = 2.f * acc.x - p.x; acc.y = 2.f * acc.y - p.y;
    acc.z = 2.f * acc.z - p.z; acc.w = 2.f * acc.w - p.w;
    ((float4*)(d_T + (size_t)2 * VV * 64))[tid] = acc;
}

__global__ void __launch_bounds__(256) k_spmm1_rest(int kin, int kp2, int kout,
                                                    const float* __restrict__ vals,
                                                    const int* __restrict__ cols) {
    int tid = blockIdx.x * 256 + threadIdx.x;
    int v = tid >> 4, d4 = tid & 15;
    const float4* tin = (const float4*)(d_T + (size_t)kin * VV * 64);
    float4 acc = make_float4(0.f, 0.f, 0.f, 0.f);
#pragma unroll
    for (int j = 0; j < NNZ; ++j) {
        int c = __ldg(&cols[v * NNZ + j]);
        float w = __ldg(&vals[v * NNZ + j]);
        float4 t = __ldg(&tin[(size_t)c * 16 + d4]);
        acc.x += w * t.x; acc.y += w * t.y; acc.z += w * t.z; acc.w += w * t.w;
    }
    float4 p = ((const float4*)(d_T + (size_t)kp2 * VV * 64))[tid];
    acc.x = 2.f * acc.x - p.x; acc.y = 2.f * acc.y - p.y;
    acc.z = 2.f * acc.z - p.z; acc.w = 2.f * acc.w - p.w;
    ((float4*)(d_T + (size_t)kout * VV * 64))[tid] = acc;
}

// ---------------- block2 SPMM family (D=128, 4 floats/thread) ----------------
template <bool FIRST>
__global__ void __launch_bounds__(256) k_spmm2(int kin, int kp2, int kout,
                                               const float* __restrict__ vals,
                                               const int* __restrict__ cols) {
    int tid = blockIdx.x * 256 + threadIdx.x;
    int v = tid >> 5, d4 = tid & 31;
    const float4* tin = (const float4*)(d_U + (size_t)kin * VV * 128);
    float4 acc = make_float4(0.f, 0.f, 0.f, 0.f);
#pragma unroll
    for (int j = 0; j < NNZ; ++j) {
        int c = __ldg(&cols[v * NNZ + j]);
        float w = __ldg(&vals[v * NNZ + j]);
        float4 t = __ldg(&tin[(size_t)c * 32 + d4]);
        acc.x += w * t.x; acc.y += w * t.y; acc.z += w * t.z; acc.w += w * t.w;
    }
    if (!FIRST) {
        float4 p = ((const float4*)(d_U + (size_t)kp2 * VV * 128))[tid];
        acc.x = 2.f * acc.x - p.x; acc.y = 2.f * acc.y - p.y;
        acc.z = 2.f * acc.z - p.z; acc.w = 2.f * acc.w - p.w;
    }
    ((float4*)(d_U + (size_t)kout * VV * 128))[tid] = acc;
}

// ---------------- GEMM 1: [98304 x 256] @ [256 x 128] (W1|Wr), cp.async pipelined ----------
// Chunk 0 A = x directly; chunks 1..7 = d_T. Cols 0..63 -> d_U(+b1); 64..127 -> d_res(+br).
// GN1 stats fused into epilogue (8-way spread atomics).
__global__ void __launch_bounds__(256) k_gemm1_mma(const float* __restrict__ x,
                                                   const float* __restrict__ b1,
                                                   const float* __restrict__ br) {
    extern __shared__ float smem[];
    float (*As)[128][36] = (float(*)[128][36])smem;                 // 2 x 18 KB
    float (*Bs)[128][36] = (float(*)[128][36])(smem + 2 * 128 * 36); // 2 x 18 KB
    int v0 = blockIdx.x * 64;
    int tid = threadIdx.x;
    int warp = tid >> 5, lane = tid & 31;
    int g = lane >> 2, t = lane & 3;
    int wm = warp >> 1, wn = warp & 1;  // 4 x 2 warps
    int m_w = wm * 32, n_w = wn * 64;

    float acc[2][8][4];
#pragma unroll
    for (int mi = 0; mi < 2; ++mi)
#pragma unroll
        for (int ni = 0; ni < 8; ++ni)
#pragma unroll
            for (int q = 0; q < 4; ++q) acc[mi][ni][q] = 0.f;

    // stage chunk c into buffer buf
    auto stage = [&](int c, int buf) {
        if (c == 0) {
            const float4* xs = (const float4*)x;
#pragma unroll
            for (int tl = 0; tl < 4; ++tl) {
                int lt4 = tid + tl * 256;
                int voff = lt4 >> 4, bb = (lt4 >> 3) & 1, f4 = lt4 & 7;
                cpasync16(&As[buf][voff * 2 + bb][f4 * 4],
                          xs + ((size_t)bb * VV + v0 + voff) * 8 + f4);
            }
        } else {
            const float4* asrc = (const float4*)(d_T + (size_t)c * VV * 64 + (size_t)v0 * 64);
#pragma unroll
            for (int tl = 0; tl < 4; ++tl) {
                int lt4 = tid + tl * 256;
                int lt = lt4 * 4;
                int r = ((lt >> 6) << 1) | ((lt >> 5) & 1);
                cpasync16(&As[buf][r][lt & 31], asrc + lt4);
            }
        }
        const float4* bsrc = (const float4*)d_Bt1 + c * 1024;
#pragma unroll
        for (int tl = 0; tl < 4; ++tl) {
            int lt4 = tid + tl * 256;
            int lt = lt4 * 4;
            cpasync16(&Bs[buf][lt >> 5][lt & 31], bsrc + lt4);
        }
    };

    stage(0, 0);
    CP_COMMIT();
#pragma unroll 1
    for (int c = 0; c < 8; ++c) {
        int cb = c & 1;
        if (c < 7) {
            stage(c + 1, cb ^ 1);
            CP_COMMIT();
            CP_WAIT(1);
        } else {
            CP_WAIT(0);
        }
        __syncthreads();
#pragma unroll
        for (int ks = 0; ks < 4; ++ks) {
            int k0 = ks * 8;
            uint32_t a[2][4];
#pragma unroll
            for (int mi = 0; mi < 2; ++mi) {
                int m = m_w + mi * 16;
                a[mi][0] = u_tf32(As[cb][m + g][k0 + t]);
                a[mi][1] = u_tf32(As[cb][m + g + 8][k0 + t]);
                a[mi][2] = u_tf32(As[cb][m + g][k0 + t + 4]);
                a[mi][3] = u_tf32(As[cb][m + g + 8][k0 + t + 4]);
            }
#pragma unroll
            for (int ni = 0; ni < 8; ++ni) {
                int n = n_w + ni * 8;
                uint32_t b0 = __float_as_uint(Bs[cb][n + g][k0 + t]);
                uint32_t b1v = __float_as_uint(Bs[cb][n + g][k0 + t + 4]);
#pragma unroll
                for (int mi = 0; mi < 2; ++mi)
                    mma_tf32(acc[mi][ni], a[mi][0], a[mi][1], a[mi][2], a[mi][3], b0, b1v);
            }
        }
        __syncthreads();
    }
    // epilogue + fused GN1 stats (cols 0..63 only -> wn==0 warps)
    float sni[8], s2ni[8];
#pragma unroll
    for (int ni = 0; ni < 8; ++ni) { sni[ni] = 0.f; s2ni[ni] = 0.f; }
#pragma unroll
    for (int mi = 0; mi < 2; ++mi) {
        int r1 = m_w + mi * 16 + g;
        int v1 = v0 + (r1 >> 1), bb1 = r1 & 1;
        int r2 = r1 + 8;
        int v2 = v0 + (r2 >> 1), bb2 = r2 & 1;
#pragma unroll
        for (int ni = 0; ni < 8; ++ni) {
            int n = n_w + ni * 8 + t * 2;
            float2 p1 = make_float2(acc[mi][ni][0], acc[mi][ni][1]);
            float2 p2 = make_float2(acc[mi][ni][2], acc[mi][ni][3]);
            if (n < 64) {
                float bx = __ldg(&b1[n]), by = __ldg(&b1[n + 1]);
                p1.x += bx; p1.y += by; p2.x += bx; p2.y += by;
                *(float2*)(d_U + (size_t)v1 * 128 + bb1 * 64 + n) = p1;
                *(float2*)(d_U + (size_t)v2 * 128 + bb2 * 64 + n) = p2;
                sni[ni] += p1.x + p1.y + p2.x + p2.y;
                s2ni[ni] += p1.x * p1.x + p1.y * p1.y + p2.x * p2.x + p2.y * p2.y;
            } else {
                int o = n - 64;
                float bx = __ldg(&br[o]), by = __ldg(&br[o + 1]);
                p1.x += bx; p1.y += by; p2.x += bx; p2.y += by;
                *(float2*)(d_res + (size_t)bb1 * VV * 64 + (size_t)v1 * 64 + o) = p1;
                *(float2*)(d_res + (size_t)bb2 * VV * 64 + (size_t)v2 * 64 + o) = p2;
            }
        }
    }
    if (wn == 0) {
        float* sb = d_stats + (blockIdx.x & 7) * 64;
#pragma unroll
        for (int ni = 0; ni < 8; ++ni) {
            float s = sni[ni], s2 = s2ni[ni];
            red_stats(s, s2);
            if ((lane & 0x1B) == 0) {  // lanes 0 (b=0), 4 (b=1)
                int bb = (lane >> 2) & 1;
                atomicAdd(&sb[(bb * 8 + ni) * 2], s);
                atomicAdd(&sb[(bb * 8 + ni) * 2 + 1], s2);
            }
        }
    }
}

// ---------------- GEMM 2: [98304 x 512] @ [512 x 64] (W2), cp.async pipelined ------------
// GN2 stats fused into epilogue.
__global__ void __launch_bounds__(256) k_gemm2_mma(const float* __restrict__ b2,
                                                   float* __restrict__ out) {
    extern __shared__ float smem[];
    float (*As)[128][36] = (float(*)[128][36])smem;                 // 2 x 18 KB
    float (*Bs)[64][36] = (float(*)[64][36])(smem + 2 * 128 * 36);  // 2 x 9 KB
    int v0 = blockIdx.x * 64;
    int tid = threadIdx.x;
    int warp = tid >> 5, lane = tid & 31;
    int g = lane >> 2, t = lane & 3;
    int m_w = warp * 16;  // 8 warps along M

    float acc[8][4];
#pragma unroll
    for (int ni = 0; ni < 8; ++ni)
#pragma unroll
        for (int q = 0; q < 4; ++q) acc[ni][q] = 0.f;

    auto stage = [&](int c, int buf) {
        int kk = c >> 1, f0 = (c & 1) * 32;
        const float4* asrc = (const float4*)(d_U + (size_t)kk * VV * 128 + (size_t)v0 * 128 + f0);
#pragma unroll
        for (int tl = 0; tl < 4; ++tl) {
            int lt4 = tid + tl * 256;
            int r = lt4 >> 3, f4 = lt4 & 7;
            cpasync16(&As[buf][r][f4 * 4], asrc + (r >> 1) * 32 + (r & 1) * 16 + f4);
        }
        const float4* bsrc = (const float4*)d_Bt2 + c * 512;
#pragma unroll
        for (int tl = 0; tl < 2; ++tl) {
            int lt4 = tid + tl * 256;
            int lt = lt4 * 4;
            cpasync16(&Bs[buf][lt >> 5][lt & 31], bsrc + lt4);
        }
    };

    stage(0, 0);
    CP_COMMIT();
#pragma unroll 1
    for (int c = 0; c < 16; ++c) {
        int cb = c & 1;
        if (c < 15) {
            stage(c + 1, cb ^ 1);
            CP_COMMIT();
            CP_WAIT(1);
        } else {
            CP_WAIT(0);
        }
        __syncthreads();
#pragma unroll
        for (int ks = 0; ks < 4; ++ks) {
            int k0 = ks * 8;
            uint32_t a0 = u_tf32(As[cb][m_w + g][k0 + t]);
            uint32_t a1 = u_tf32(As[cb][m_w + g + 8][k0 + t]);
            uint32_t a2 = u_tf32(As[cb][m_w + g][k0 + t + 4]);
            uint32_t a3 = u_tf32(As[cb][m_w + g + 8][k0 + t + 4]);
#pragma unroll
            for (int ni = 0; ni < 8; ++ni) {
                int n = ni * 8;
                uint32_t b0 = __float_as_uint(Bs[cb][n + g][k0 + t]);
                uint32_t b1v = __float_as_uint(Bs[cb][n + g][k0 + t + 4]);
                mma_tf32(acc[ni], a0, a1, a2, a3, b0, b1v);
            }
        }
        __syncthreads();
    }
    int r1 = m_w + g;
    int v1 = v0 + (r1 >> 1), bb1 = r1 & 1;
    int r2 = r1 + 8;
    int v2 = v0 + (r2 >> 1), bb2 = r2 & 1;
    float* o1 = out + (size_t)bb1 * VV * 64 + (size_t)v1 * 64;
    float* o2 = out + (size_t)bb2 * VV * 64 + (size_t)v2 * 64;
    float* sb = d_stats + (blockIdx.x & 7) * 64;
#pragma unroll
    for (int ni = 0; ni < 8; ++ni) {
        int n = ni * 8 + t * 2;
        float bx = __ldg(&b2[n]), by = __ldg(&b2[n + 1]);
        float e0 = acc[ni][0] + bx, e1 = acc[ni][1] + by;
        float e2 = acc[ni][2] + bx, e3 = acc[ni][3] + by;
        *(float2*)(o1 + n) = make_float2(e0, e1);
        *(float2*)(o2 + n) = make_float2(e2, e3);
        float s = e0 + e1 + e2 + e3;
        float s2 = e0 * e0 + e1 * e1 + e2 * e2 + e3 * e3;
        red_stats(s, s2);
        if ((lane & 0x1B) == 0) {
            int bb = (lane >> 2) & 1;
            atomicAdd(&sb[32 + (bb * 8 + ni) * 2], s);
            atomicAdd(&sb[32 + (bb * 8 + ni) * 2 + 1], s2);
        }
    }
}

// ---------------- GN apply + LeakyReLU (reads 8 spread stat buffers) ----------------
__global__ void k_gnapply1(const float* __restrict__ gamma, const float* __restrict__ beta) {
    int idx = blockIdx.x * blockDim.x + threadIdx.x;
    if (idx >= VV * 128) return;
    int rem = idx & 127, b = rem >> 6, c = rem & 63, g = c >> 3;
    int bin = (b * 8 + g) * 2;
    float s = 0.f, s2 = 0.f;
#pragma unroll
    for (int p = 0; p < 8; ++p) { s += d_stats[p * 64 + bin]; s2 += d_stats[p * 64 + bin + 1]; }
    float mu = s / GN_N;
    float var = s2 / GN_N - mu * mu;
    float rstd = rsqrtf(var + 1e-5f);
    float y = (d_U[idx] - mu) * rstd * gamma[c] + beta[c];
    d_U[idx] = fmaxf(y, 0.1f * y);
}

__global__ void k_final(float* __restrict__ out,
                        const float* __restrict__ gamma, const float* __restrict__ beta) {
    int idx = blockIdx.x * blockDim.x + threadIdx.x;
    if (idx >= 2 * VV * 64) return;
    int b = idx / (VV * 64);
    int c = idx & 63, g = c >> 3;
    int bin = 32 + (b * 8 + g) * 2;
    float s = 0.f, s2 = 0.f;
#pragma unroll
    for (int p = 0; p < 8; ++p) { s += d_stats[p * 64 + bin]; s2 += d_stats[p * 64 + bin + 1]; }
    float mu = s / GN_N;
    float var = s2 / GN_N - mu * mu;
    float rstd = rsqrtf(var + 1e-5f);
    float y = (out[idx] - mu) * rstd * gamma[c] + beta[c];
    out[idx] = fmaxf(y, 0.1f * y) + d_res[idx];
}

// ---------------- launch ----------------
extern "C" void kernel_launch(void* const* d_in, const int* in_sizes, int n_in,
                              void* d_out, int out_size) {
    const float* x    = (const float*)d_in[0];
    const float* vals = (const float*)d_in[1];
    const int*   cols = (const int*)d_in[3];
    const float* W1 = (const float*)d_in[4];
    const float* b1 = (const float*)d_in[5];
    const float* g1 = (const float*)d_in[6];
    const float* be1 = (const float*)d_in[7];
    const float* W2 = (const float*)d_in[8];
    const float* b2 = (const float*)d_in[9];
    const float* g2 = (const float*)d_in[10];
    const float* be2 = (const float*)d_in[11];
    const float* Wr = (const float*)d_in[12];
    const float* br = (const float*)d_in[13];
    float* out = (float*)d_out;

    const int SMEM1 = 4 * 128 * 36 * 4;                  // 73728 B
    const int SMEM2 = (2 * 128 * 36 + 2 * 64 * 36) * 4;  // 55296 B
    cudaFuncSetAttribute(k_gemm1_mma, cudaFuncAttributeMaxDynamicSharedMemorySize, SMEM1);
    cudaFuncSetAttribute(k_gemm2_mma, cudaFuncAttributeMaxDynamicSharedMemorySize, SMEM2);

    k_wtrans<<<(8 * 128 * 32 + 16 * 64 * 32) / 256, 256>>>(W1, Wr, W2);

    // block1 Chebyshev terms t1..t7 (t0 = x read in place)
    const int g64 = (VV * 16) / 256;
    k_spmm1_first<<<g64, 256>>>(x, vals, cols);
    k_spmm1_second<<<g64, 256>>>(x, vals, cols);
    k_spmm1_rest<<<g64, 256>>>(2, 1, 3, vals, cols);
    k_spmm1_rest<<<g64, 256>>>(3, 2, 4, vals, cols);
    k_spmm1_rest<<<g64, 256>>>(4, 3, 5, vals, cols);
    k_spmm1_rest<<<g64, 256>>>(5, 4, 6, vals, cols);
    k_spmm1_rest<<<g64, 256>>>(6, 5, 7, vals, cols);

    // h1pre (raw, into d_U[0]) + residual + fused GN1 stats
    k_gemm1_mma<<<VV / 64, 256, SMEM1>>>(x, b1, br);

    // GN1 apply (in place -> d_U[0] becomes normalized h1)
    k_gnapply1<<<(VV * 128) / 256, 256>>>(g1, be1);

    // block2 Chebyshev terms u1..u7
    const int g128 = (VV * 32) / 256;
    k_spmm2<true><<<g128, 256>>>(0, 0, 1, vals, cols);
    k_spmm2<false><<<g128, 256>>>(1, 0, 2, vals, cols);
    k_spmm2<false><<<g128, 256>>>(2, 1, 3, vals, cols);
    k_spmm2<false><<<g128, 256>>>(3, 2, 4, vals, cols);
    k_spmm2<false><<<g128, 256>>>(4, 3, 5, vals, cols);
    k_spmm2<false><<<g128, 256>>>(5, 4, 6, vals, cols);
    k_spmm2<false><<<g128, 256>>>(6, 5, 7, vals, cols);

    // h2pre -> out + fused GN2 stats
    k_gemm2_mma<<<VV / 64, 256, SMEM2>>>(b2, out);

    // GN2 + LeakyReLU + residual add
    k_final<<<(2 * VV * 64) / 256, 256>>>(out, g2, be2);
}

// round 10
// speedup vs baseline: 1.5194x; 1.0305x over previous
#include <cuda_runtime.h>
#include <cuda_fp16.h>
#include <cstdint>

#define VV 49152
#define NNZ 9
#define GN_N 393216.0f  // V * (C/G)

// ---------------- scratch (device globals; no runtime allocation) ----------------
__device__ __half d_Th[(size_t)8 * VV * 64];  // block1 terms fp16: slot0 = x, slots 1..7 = t1..t7
__device__ float d_U[(size_t)8 * VV * 128];   // slot0 = h1 (normalized in place), 1..7 = block2 terms
__device__ float d_res[(size_t)2 * VV * 64];  // residual conv output [b][v][o]
__device__ float d_stats[8 * 64];             // 8 spread buffers x [0:32) GN1, [32:64) GN2
__device__ float d_Bt1[8 * 128 * 32];         // GEMM1 B^T (W1|Wr), tf32-rounded
__device__ float d_Bt2[16 * 64 * 32];         // GEMM2 B^T (W2), tf32-rounded

// ---------------- helpers ----------------
__device__ __forceinline__ float ftf32(float x) {
    uint32_t r;
    asm("cvt.rna.tf32.f32 %0, %1;" : "=r"(r) : "f"(x));
    return __uint_as_float(r);
}
__device__ __forceinline__ uint32_t u_tf32(float x) {
    uint32_t r;
    asm("cvt.rna.tf32.f32 %0, %1;" : "=r"(r) : "f"(x));
    return r;
}
__device__ __forceinline__ void mma_tf32(float* d, uint32_t a0, uint32_t a1, uint32_t a2,
                                         uint32_t a3, uint32_t b0, uint32_t b1) {
    asm volatile(
        "mma.sync.aligned.m16n8k8.row.col.f32.tf32.tf32.f32 "
        "{%0,%1,%2,%3}, {%4,%5,%6,%7}, {%8,%9}, {%0,%1,%2,%3};"
        : "+f"(d[0]), "+f"(d[1]), "+f"(d[2]), "+f"(d[3])
        : "r"(a0), "r"(a1), "r"(a2), "r"(a3), "r"(b0), "r"(b1));
}
__device__ __forceinline__ void cpasync16(void* sptr, const void* gptr) {
    uint32_t sa = (uint32_t)__cvta_generic_to_shared(sptr);
    asm volatile("cp.async.cg.shared.global [%0], [%1], 16;" :: "r"(sa), "l"(gptr));
}
#define CP_COMMIT() asm volatile("cp.async.commit_group;" ::: "memory")
#define CP_WAIT(n)  asm volatile("cp.async.wait_group %0;" :: "n"(n) : "memory")

__device__ __forceinline__ void red_stats(float& s, float& s2) {
#pragma unroll
    for (int m = 1; m <= 16; m <<= 1) {
        if (m == 4) continue;
        s += __shfl_xor_sync(0xFFFFFFFFu, s, m);
        s2 += __shfl_xor_sync(0xFFFFFFFFu, s2, m);
    }
}

// ---------------- weight transpose (+ stats zeroing) ----------------
__global__ void k_wtrans(const float* __restrict__ W1, const float* __restrict__ Wr,
                         const float* __restrict__ W2) {
    int idx = blockIdx.x * blockDim.x + threadIdx.x;
    if (idx < 8 * 64) d_stats[idx] = 0.0f;
    if (idx < 8 * 128 * 32) {
        int kk = idx >> 12, r = idx & 4095, o = r >> 5, f = r & 31;
        float w = (o < 64) ? W1[kk * 2048 + f * 64 + o] : Wr[kk * 2048 + f * 64 + (o - 64)];
        d_Bt1[idx] = ftf32(w);
    } else if (idx < 8 * 128 * 32 + 16 * 64 * 32) {
        int j = idx - 8 * 128 * 32;
        int c = j >> 11, rr = j & 2047, o = rr >> 5, f = rr & 31;
        int kk = c >> 1, f0 = (c & 1) * 32;
        d_Bt2[j] = ftf32(W2[kk * 4096 + (f0 + f) * 64 + o]);
    }
}

// ---------------- x -> fp16 repack into d_Th slot 0: [v][b*32+f] ----------------
__global__ void __launch_bounds__(256) k_xhalf(const float* __restrict__ x) {
    int tid = blockIdx.x * 256 + threadIdx.x;  // over VV*16 (4 floats each)
    int v = tid >> 4, d = (tid & 15) * 4;
    int b = d >> 5, f = d & 31;
    float4 val = ((const float4*)x)[((size_t)b * VV + v) * 8 + (f >> 2)];
    __half2 h0 = __floats2half2_rn(val.x, val.y);
    __half2 h1 = __floats2half2_rn(val.z, val.w);
    uint2 o;
    o.x = *(uint32_t*)&h0; o.y = *(uint32_t*)&h1;
    *((uint2*)(d_Th) + tid) = o;
}

// ---------------- block1 SPMM family (fp16, 4 halves/thread) ----------------
// FIRST: t[kout] = L t[kin];  else: t[kout] = 2 L t[kin] - t[kp2]
template <bool FIRST>
__global__ void __launch_bounds__(256) k_spmm1(int kin, int kp2, int kout,
                                               const float* __restrict__ vals,
                                               const int* __restrict__ cols) {
    int tid = blockIdx.x * 256 + threadIdx.x;  // over VV*16
    int v = tid >> 4, d4 = tid & 15;
    const __half* tin = d_Th + (size_t)kin * VV * 64;
    float a0 = 0.f, a1 = 0.f, a2 = 0.f, a3 = 0.f;
#pragma unroll
    for (int j = 0; j < NNZ; ++j) {
        int c = __ldg(&cols[v * NNZ + j]);
        float w = __ldg(&vals[v * NNZ + j]);
        uint2 hv = __ldg((const uint2*)(tin + (size_t)c * 64) + d4);
        float2 f0 = __half22float2(*(__half2*)&hv.x);
        float2 f1 = __half22float2(*(__half2*)&hv.y);
        a0 += w * f0.x; a1 += w * f0.y; a2 += w * f1.x; a3 += w * f1.y;
    }
    if (!FIRST) {
        uint2 pv = *((const uint2*)(d_Th + (size_t)kp2 * VV * 64) + tid);
        float2 p0 = __half22float2(*(__half2*)&pv.x);
        float2 p1 = __half22float2(*(__half2*)&pv.y);
        a0 = 2.f * a0 - p0.x; a1 = 2.f * a1 - p0.y;
        a2 = 2.f * a2 - p1.x; a3 = 2.f * a3 - p1.y;
    }
    __half2 o0 = __floats2half2_rn(a0, a1);
    __half2 o1 = __floats2half2_rn(a2, a3);
    uint2 o;
    o.x = *(uint32_t*)&o0; o.y = *(uint32_t*)&o1;
    *((uint2*)(d_Th + (size_t)kout * VV * 64) + tid) = o;
}

// ---------------- block2 SPMM family (D=128, fp32, 4 floats/thread) ----------------
template <bool FIRST>
__global__ void __launch_bounds__(256) k_spmm2(int kin, int kp2, int kout,
                                               const float* __restrict__ vals,
                                               const int* __restrict__ cols) {
    int tid = blockIdx.x * 256 + threadIdx.x;
    int v = tid >> 5, d4 = tid & 31;
    const float4* tin = (const float4*)(d_U + (size_t)kin * VV * 128);
    float4 acc = make_float4(0.f, 0.f, 0.f, 0.f);
#pragma unroll
    for (int j = 0; j < NNZ; ++j) {
        int c = __ldg(&cols[v * NNZ + j]);
        float w = __ldg(&vals[v * NNZ + j]);
        float4 t = __ldg(&tin[(size_t)c * 32 + d4]);
        acc.x += w * t.x; acc.y += w * t.y; acc.z += w * t.z; acc.w += w * t.w;
    }
    if (!FIRST) {
        float4 p = ((const float4*)(d_U + (size_t)kp2 * VV * 128))[tid];
        acc.x = 2.f * acc.x - p.x; acc.y = 2.f * acc.y - p.y;
        acc.z = 2.f * acc.z - p.z; acc.w = 2.f * acc.w - p.w;
    }
    ((float4*)(d_U + (size_t)kout * VV * 128))[tid] = acc;
}

// ---------------- GEMM 1: [98304 x 256] @ [256 x 128] (W1|Wr), cp.async pipelined ----------
// Chunk 0 A = x (fp32, manual stage); chunks 1..7 = d_Th fp16 via cp.async.
__global__ void __launch_bounds__(256) k_gemm1_mma(const float* __restrict__ x,
                                                   const float* __restrict__ b1,
                                                   const float* __restrict__ br) {
    extern __shared__ float smem[];
    __half (*As)[128][40] = (__half(*)[128][40])smem;                   // 2 x 10 KB
    float (*Bs)[128][36] = (float(*)[128][36])(smem + 2 * 128 * 40 / 2); // 2 x 18 KB
    int v0 = blockIdx.x * 64;
    int tid = threadIdx.x;
    int warp = tid >> 5, lane = tid & 31;
    int g = lane >> 2, t = lane & 3;
    int wm = warp >> 1, wn = warp & 1;  // 4 x 2 warps
    int m_w = wm * 32, n_w = wn * 64;

    float acc[2][8][4];
#pragma unroll
    for (int mi = 0; mi < 2; ++mi)
#pragma unroll
        for (int ni = 0; ni < 8; ++ni)
#pragma unroll
            for (int q = 0; q < 4; ++q) acc[mi][ni][q] = 0.f;

    auto stageB = [&](int c, int buf) {
        const float4* bsrc = (const float4*)d_Bt1 + c * 1024;
#pragma unroll
        for (int tl = 0; tl < 4; ++tl) {
            int lt4 = tid + tl * 256;
            int lt = lt4 * 4;
            cpasync16(&Bs[buf][lt >> 5][lt & 31], bsrc + lt4);
        }
    };
    auto stageA = [&](int c, int buf) {  // c >= 1 only (fp16 cp.async)
        const __half* asrc = d_Th + (size_t)c * VV * 64 + (size_t)v0 * 64;
#pragma unroll
        for (int tl = 0; tl < 2; ++tl) {
            int lt8 = tid + tl * 256;
            int voff = lt8 >> 3, h0 = (lt8 & 7) * 8;
            int bb = h0 >> 5, f = h0 & 31;
            cpasync16(&As[buf][voff * 2 + bb][f], asrc + voff * 64 + h0);
        }
    };

    // prologue: chunk0 A manual (x fp32 -> half), B0 via cp.async
    {
        const float4* xs = (const float4*)x;
#pragma unroll
        for (int tl = 0; tl < 4; ++tl) {
            int lt4 = tid + tl * 256;
            int voff = lt4 >> 4, bb = (lt4 >> 3) & 1, f4 = lt4 & 7;
            float4 val = xs[((size_t)bb * VV + v0 + voff) * 8 + f4];
            __half2 h0 = __floats2half2_rn(val.x, val.y);
            __half2 h1 = __floats2half2_rn(val.z, val.w);
            uint2 o;
            o.x = *(uint32_t*)&h0; o.y = *(uint32_t*)&h1;
            *(uint2*)&As[0][voff * 2 + bb][f4 * 4] = o;
        }
        stageB(0, 0);
        CP_COMMIT();
    }
#pragma unroll 1
    for (int c = 0; c < 8; ++c) {
        int cb = c & 1;
        if (c < 7) {
            stageA(c + 1, cb ^ 1);
            stageB(c + 1, cb ^ 1);
            CP_COMMIT();
            CP_WAIT(1);
        } else {
            CP_WAIT(0);
        }
        __syncthreads();
#pragma unroll
        for (int ks = 0; ks < 4; ++ks) {
            int k0 = ks * 8;
            uint32_t a[2][4];
#pragma unroll
            for (int mi = 0; mi < 2; ++mi) {
                int m = m_w + mi * 16;
                a[mi][0] = u_tf32(__half2float(As[cb][m + g][k0 + t]));
                a[mi][1] = u_tf32(__half2float(As[cb][m + g + 8][k0 + t]));
                a[mi][2] = u_tf32(__half2float(As[cb][m + g][k0 + t + 4]));
                a[mi][3] = u_tf32(__half2float(As[cb][m + g + 8][k0 + t + 4]));
            }
#pragma unroll
            for (int ni = 0; ni < 8; ++ni) {
                int n = n_w + ni * 8;
                uint32_t b0 = __float_as_uint(Bs[cb][n + g][k0 + t]);
                uint32_t b1v = __float_as_uint(Bs[cb][n + g][k0 + t + 4]);
#pragma unroll
                for (int mi = 0; mi < 2; ++mi)
                    mma_tf32(acc[mi][ni], a[mi][0], a[mi][1], a[mi][2], a[mi][3], b0, b1v);
            }
        }
        __syncthreads();
    }
    // epilogue + fused GN1 stats
    float sni[8], s2ni[8];
#pragma unroll
    for (int ni = 0; ni < 8; ++ni) { sni[ni] = 0.f; s2ni[ni] = 0.f; }
#pragma unroll
    for (int mi = 0; mi < 2; ++mi) {
        int r1 = m_w + mi * 16 + g;
        int v1 = v0 + (r1 >> 1), bb1 = r1 & 1;
        int r2 = r1 + 8;
        int v2 = v0 + (r2 >> 1), bb2 = r2 & 1;
#pragma unroll
        for (int ni = 0; ni < 8; ++ni) {
            int n = n_w + ni * 8 + t * 2;
            float2 p1 = make_float2(acc[mi][ni][0], acc[mi][ni][1]);
            float2 p2 = make_float2(acc[mi][ni][2], acc[mi][ni][3]);
            if (n < 64) {
                float bx = __ldg(&b1[n]), by = __ldg(&b1[n + 1]);
                p1.x += bx; p1.y += by; p2.x += bx; p2.y += by;
                *(float2*)(d_U + (size_t)v1 * 128 + bb1 * 64 + n) = p1;
                *(float2*)(d_U + (size_t)v2 * 128 + bb2 * 64 + n) = p2;
                sni[ni] += p1.x + p1.y + p2.x + p2.y;
                s2ni[ni] += p1.x * p1.x + p1.y * p1.y + p2.x * p2.x + p2.y * p2.y;
            } else {
                int o = n - 64;
                float bx = __ldg(&br[o]), by = __ldg(&br[o + 1]);
                p1.x += bx; p1.y += by; p2.x += bx; p2.y += by;
                *(float2*)(d_res + (size_t)bb1 * VV * 64 + (size_t)v1 * 64 + o) = p1;
                *(float2*)(d_res + (size_t)bb2 * VV * 64 + (size_t)v2 * 64 + o) = p2;
            }
        }
    }
    if (wn == 0) {
        float* sb = d_stats + (blockIdx.x & 7) * 64;
#pragma unroll
        for (int ni = 0; ni < 8; ++ni) {
            float s = sni[ni], s2 = s2ni[ni];
            red_stats(s, s2);
            if ((lane & 0x1B) == 0) {
                int bb = (lane >> 2) & 1;
                atomicAdd(&sb[(bb * 8 + ni) * 2], s);
                atomicAdd(&sb[(bb * 8 + ni) * 2 + 1], s2);
            }
        }
    }
}

// ---------------- GEMM 2: [98304 x 512] @ [512 x 64] (W2), cp.async pipelined ------------
__global__ void __launch_bounds__(256) k_gemm2_mma(const float* __restrict__ b2,
                                                   float* __restrict__ out) {
    extern __shared__ float smem[];
    float (*As)[128][36] = (float(*)[128][36])smem;
    float (*Bs)[64][36] = (float(*)[64][36])(smem + 2 * 128 * 36);
    int v0 = blockIdx.x * 64;
    int tid = threadIdx.x;
    int warp = tid >> 5, lane = tid & 31;
    int g = lane >> 2, t = lane & 3;
    int m_w = warp * 16;

    float acc[8][4];
#pragma unroll
    for (int ni = 0; ni < 8; ++ni)
#pragma unroll
        for (int q = 0; q < 4; ++q) acc[ni][q] = 0.f;

    auto stage = [&](int c, int buf) {
        int kk = c >> 1, f0 = (c & 1) * 32;
        const float4* asrc = (const float4*)(d_U + (size_t)kk * VV * 128 + (size_t)v0 * 128 + f0);
#pragma unroll
        for (int tl = 0; tl < 4; ++tl) {
            int lt4 = tid + tl * 256;
            int r = lt4 >> 3, f4 = lt4 & 7;
            cpasync16(&As[buf][r][f4 * 4], asrc + (r >> 1) * 32 + (r & 1) * 16 + f4);
        }
        const float4* bsrc = (const float4*)d_Bt2 + c * 512;
#pragma unroll
        for (int tl = 0; tl < 2; ++tl) {
            int lt4 = tid + tl * 256;
            int lt = lt4 * 4;
            cpasync16(&Bs[buf][lt >> 5][lt & 31], bsrc + lt4);
        }
    };

    stage(0, 0);
    CP_COMMIT();
#pragma unroll 1
    for (int c = 0; c < 16; ++c) {
        int cb = c & 1;
        if (c < 15) {
            stage(c + 1, cb ^ 1);
            CP_COMMIT();
            CP_WAIT(1);
        } else {
            CP_WAIT(0);
        }
        __syncthreads();
#pragma unroll
        for (int ks = 0; ks < 4; ++ks) {
            int k0 = ks * 8;
            uint32_t a0 = u_tf32(As[cb][m_w + g][k0 + t]);
            uint32_t a1 = u_tf32(As[cb][m_w + g + 8][k0 + t]);
            uint32_t a2 = u_tf32(As[cb][m_w + g][k0 + t + 4]);
            uint32_t a3 = u_tf32(As[cb][m_w + g + 8][k0 + t + 4]);
#pragma unroll
            for (int ni = 0; ni < 8; ++ni) {
                int n = ni * 8;
                uint32_t b0 = __float_as_uint(Bs[cb][n + g][k0 + t]);
                uint32_t b1v = __float_as_uint(Bs[cb][n + g][k0 + t + 4]);
                mma_tf32(acc[ni], a0, a1, a2, a3, b0, b1v);
            }
        }
        __syncthreads();
    }
    int r1 = m_w + g;
    int v1 = v0 + (r1 >> 1), bb1 = r1 & 1;
    int r2 = r1 + 8;
    int v2 = v0 + (r2 >> 1), bb2 = r2 & 1;
    float* o1 = out + (size_t)bb1 * VV * 64 + (size_t)v1 * 64;
    float* o2 = out + (size_t)bb2 * VV * 64 + (size_t)v2 * 64;
    float* sb = d_stats + (blockIdx.x & 7) * 64;
#pragma unroll
    for (int ni = 0; ni < 8; ++ni) {
        int n = ni * 8 + t * 2;
        float bx = __ldg(&b2[n]), by = __ldg(&b2[n + 1]);
        float e0 = acc[ni][0] + bx, e1 = acc[ni][1] + by;
        float e2 = acc[ni][2] + bx, e3 = acc[ni][3] + by;
        *(float2*)(o1 + n) = make_float2(e0, e1);
        *(float2*)(o2 + n) = make_float2(e2, e3);
        float s = e0 + e1 + e2 + e3;
        float s2 = e0 * e0 + e1 * e1 + e2 * e2 + e3 * e3;
        red_stats(s, s2);
        if ((lane & 0x1B) == 0) {
            int bb = (lane >> 2) & 1;
            atomicAdd(&sb[32 + (bb * 8 + ni) * 2], s);
            atomicAdd(&sb[32 + (bb * 8 + ni) * 2 + 1], s2);
        }
    }
}

// ---------------- GN apply + LeakyReLU ----------------
__global__ void k_gnapply1(const float* __restrict__ gamma, const float* __restrict__ beta) {
    int idx = blockIdx.x * blockDim.x + threadIdx.x;
    if (idx >= VV * 128) return;
    int rem = idx & 127, b = rem >> 6, c = rem & 63, g = c >> 3;
    int bin = (b * 8 + g) * 2;
    float s = 0.f, s2 = 0.f;
#pragma unroll
    for (int p = 0; p < 8; ++p) { s += d_stats[p * 64 + bin]; s2 += d_stats[p * 64 + bin + 1]; }
    float mu = s / GN_N;
    float var = s2 / GN_N - mu * mu;
    float rstd = rsqrtf(var + 1e-5f);
    float y = (d_U[idx] - mu) * rstd * gamma[c] + beta[c];
    d_U[idx] = fmaxf(y, 0.1f * y);
}

__global__ void k_final(float* __restrict__ out,
                        const float* __restrict__ gamma, const float* __restrict__ beta) {
    int idx = blockIdx.x * blockDim.x + threadIdx.x;
    if (idx >= 2 * VV * 64) return;
    int b = idx / (VV * 64);
    int c = idx & 63, g = c >> 3;
    int bin = 32 + (b * 8 + g) * 2;
    float s = 0.f, s2 = 0.f;
#pragma unroll
    for (int p = 0; p < 8; ++p) { s += d_stats[p * 64 + bin]; s2 += d_stats[p * 64 + bin + 1]; }
    float mu = s / GN_N;
    float var = s2 / GN_N - mu * mu;
    float rstd = rsqrtf(var + 1e-5f);
    float y = (out[idx] - mu) * rstd * gamma[c] + beta[c];
    out[idx] = fmaxf(y, 0.1f * y) + d_res[idx];
}

// ---------------- launch ----------------
extern "C" void kernel_launch(void* const* d_in, const int* in_sizes, int n_in,
                              void* d_out, int out_size) {
    const float* x    = (const float*)d_in[0];
    const float* vals = (const float*)d_in[1];
    const int*   cols = (const int*)d_in[3];
    const float* W1 = (const float*)d_in[4];
    const float* b1 = (const float*)d_in[5];
    const float* g1 = (const float*)d_in[6];
    const float* be1 = (const float*)d_in[7];
    const float* W2 = (const float*)d_in[8];
    const float* b2 = (const float*)d_in[9];
    const float* g2 = (const float*)d_in[10];
    const float* be2 = (const float*)d_in[11];
    const float* Wr = (const float*)d_in[12];
    const float* br = (const float*)d_in[13];
    float* out = (float*)d_out;

    const int SMEM1 = 2 * 128 * 40 * 2 + 2 * 128 * 36 * 4;  // 20480 + 36864 = 57344 B
    const int SMEM2 = (2 * 128 * 36 + 2 * 64 * 36) * 4;     // 55296 B
    cudaFuncSetAttribute(k_gemm1_mma, cudaFuncAttributeMaxDynamicSharedMemorySize, SMEM1);
    cudaFuncSetAttribute(k_gemm2_mma, cudaFuncAttributeMaxDynamicSharedMemorySize, SMEM2);

    k_wtrans<<<(8 * 128 * 32 + 16 * 64 * 32) / 256, 256>>>(W1, Wr, W2);
    k_xhalf<<<(VV * 16) / 256, 256>>>(x);

    // block1 Chebyshev terms t1..t7 in fp16 (t0 = xh in slot 0)
    const int g64 = (VV * 16) / 256;
    k_spmm1<true><<<g64, 256>>>(0, 0, 1, vals, cols);
    k_spmm1<false><<<g64, 256>>>(1, 0, 2, vals, cols);
    k_spmm1<false><<<g64, 256>>>(2, 1, 3, vals, cols);
    k_spmm1<false><<<g64, 256>>>(3, 2, 4, vals, cols);
    k_spmm1<false><<<g64, 256>>>(4, 3, 5, vals, cols);
    k_spmm1<false><<<g64, 256>>>(5, 4, 6, vals, cols);
    k_spmm1<false><<<g64, 256>>>(6, 5, 7, vals, cols);

    // h1pre (raw, into d_U[0]) + residual + fused GN1 stats
    k_gemm1_mma<<<VV / 64, 256, SMEM1>>>(x, b1, br);

    // GN1 apply (in place)
    k_gnapply1<<<(VV * 128) / 256, 256>>>(g1, be1);

    // block2 Chebyshev terms u1..u7 (fp32)
    const int g128 = (VV * 32) / 256;
    k_spmm2<true><<<g128, 256>>>(0, 0, 1, vals, cols);
    k_spmm2<false><<<g128, 256>>>(1, 0, 2, vals, cols);
    k_spmm2<false><<<g128, 256>>>(2, 1, 3, vals, cols);
    k_spmm2<false><<<g128, 256>>>(3, 2, 4, vals, cols);
    k_spmm2<false><<<g128, 256>>>(4, 3, 5, vals, cols);
    k_spmm2<false><<<g128, 256>>>(5, 4, 6, vals, cols);
    k_spmm2<false><<<g128, 256>>>(6, 5, 7, vals, cols);

    // h2pre -> out + fused GN2 stats
    k_gemm2_mma<<<VV / 64, 256, SMEM2>>>(b2, out);

    // GN2 + LeakyReLU + residual add
    k_final<<<(2 * VV * 64) / 256, 256>>>(out, g2, be2);
}

// round 11
// speedup vs baseline: 1.8698x; 1.2306x over previous
#include <cuda_runtime.h>
#include <cuda_fp16.h>
#include <cstdint>

#define VV 49152
#define NNZ 9
#define GN_N 393216.0f  // V * (C/G)

// ---------------- scratch (device globals; no runtime allocation) ----------------
__device__ __half d_Th[(size_t)8 * VV * 64];   // block1 terms fp16: slot0 = x, 1..7 = t1..t7
__device__ __half d_Uh[(size_t)8 * VV * 128];  // block2 terms fp16: slot0 = normalized h1, 1..7 = u1..u7
__device__ float d_h1[(size_t)VV * 128];       // raw h1pre fp32 (GEMM1 out)
__device__ float d_res[(size_t)2 * VV * 64];   // residual conv output [b][v][o]
__device__ float d_stats[8 * 64];              // 8 spread buffers x [GN1 | GN2] (sum,sumsq)x16
__device__ float d_Bt1[8 * 128 * 32];          // GEMM1 B^T (W1|Wr), tf32-rounded
__device__ float d_Bt2[16 * 64 * 32];          // GEMM2 B^T (W2), tf32-rounded

// ---------------- helpers ----------------
__device__ __forceinline__ float ftf32(float x) {
    uint32_t r;
    asm("cvt.rna.tf32.f32 %0, %1;" : "=r"(r) : "f"(x));
    return __uint_as_float(r);
}
__device__ __forceinline__ uint32_t u_tf32(float x) {
    uint32_t r;
    asm("cvt.rna.tf32.f32 %0, %1;" : "=r"(r) : "f"(x));
    return r;
}
__device__ __forceinline__ void mma_tf32(float* d, uint32_t a0, uint32_t a1, uint32_t a2,
                                         uint32_t a3, uint32_t b0, uint32_t b1) {
    asm volatile(
        "mma.sync.aligned.m16n8k8.row.col.f32.tf32.tf32.f32 "
        "{%0,%1,%2,%3}, {%4,%5,%6,%7}, {%8,%9}, {%0,%1,%2,%3};"
        : "+f"(d[0]), "+f"(d[1]), "+f"(d[2]), "+f"(d[3])
        : "r"(a0), "r"(a1), "r"(a2), "r"(a3), "r"(b0), "r"(b1));
}
__device__ __forceinline__ void cpasync16(void* sptr, const void* gptr) {
    uint32_t sa = (uint32_t)__cvta_generic_to_shared(sptr);
    asm volatile("cp.async.cg.shared.global [%0], [%1], 16;" :: "r"(sa), "l"(gptr));
}
#define CP_COMMIT() asm volatile("cp.async.commit_group;" ::: "memory")
#define CP_WAIT(n)  asm volatile("cp.async.wait_group %0;" :: "n"(n) : "memory")

__device__ __forceinline__ void red_stats(float& s, float& s2) {
#pragma unroll
    for (int m = 1; m <= 16; m <<= 1) {
        if (m == 4) continue;
        s += __shfl_xor_sync(0xFFFFFFFFu, s, m);
        s2 += __shfl_xor_sync(0xFFFFFFFFu, s2, m);
    }
}
// unpack uint4 (8 halves) -> 8 floats
__device__ __forceinline__ void h8_to_f8(uint4 hv, float* f) {
    float2 q0 = __half22float2(*(__half2*)&hv.x);
    float2 q1 = __half22float2(*(__half2*)&hv.y);
    float2 q2 = __half22float2(*(__half2*)&hv.z);
    float2 q3 = __half22float2(*(__half2*)&hv.w);
    f[0] = q0.x; f[1] = q0.y; f[2] = q1.x; f[3] = q1.y;
    f[4] = q2.x; f[5] = q2.y; f[6] = q3.x; f[7] = q3.y;
}
__device__ __forceinline__ uint4 f8_to_h8(const float* f) {
    uint4 o;
    __half2 h0 = __floats2half2_rn(f[0], f[1]);
    __half2 h1 = __floats2half2_rn(f[2], f[3]);
    __half2 h2 = __floats2half2_rn(f[4], f[5]);
    __half2 h3 = __floats2half2_rn(f[6], f[7]);
    o.x = *(uint32_t*)&h0; o.y = *(uint32_t*)&h1;
    o.z = *(uint32_t*)&h2; o.w = *(uint32_t*)&h3;
    return o;
}

// ---------------- weight transpose (+ stats zeroing) ----------------
__global__ void k_wtrans(const float* __restrict__ W1, const float* __restrict__ Wr,
                         const float* __restrict__ W2) {
    int idx = blockIdx.x * blockDim.x + threadIdx.x;
    if (idx < 8 * 64) d_stats[idx] = 0.0f;
    if (idx < 8 * 128 * 32) {
        int kk = idx >> 12, r = idx & 4095, o = r >> 5, f = r & 31;
        float w = (o < 64) ? W1[kk * 2048 + f * 64 + o] : Wr[kk * 2048 + f * 64 + (o - 64)];
        d_Bt1[idx] = ftf32(w);
    } else if (idx < 8 * 128 * 32 + 16 * 64 * 32) {
        int j = idx - 8 * 128 * 32;
        int c = j >> 11, rr = j & 2047, o = rr >> 5, f = rr & 31;
        int kk = c >> 1, f0 = (c & 1) * 32;
        d_Bt2[j] = ftf32(W2[kk * 4096 + (f0 + f) * 64 + o]);
    }
}

// ---------------- x -> fp16 repack into d_Th slot 0: [v][b*32+f] ----------------
__global__ void __launch_bounds__(256) k_xhalf(const float* __restrict__ x) {
    int tid = blockIdx.x * 256 + threadIdx.x;  // over VV*16 (4 floats each)
    int v = tid >> 4, d = (tid & 15) * 4;
    int b = d >> 5, f = d & 31;
    float4 val = ((const float4*)x)[((size_t)b * VV + v) * 8 + (f >> 2)];
    __half2 h0 = __floats2half2_rn(val.x, val.y);
    __half2 h1 = __floats2half2_rn(val.z, val.w);
    uint2 o;
    o.x = *(uint32_t*)&h0; o.y = *(uint32_t*)&h1;
    *((uint2*)(d_Th) + tid) = o;
}

// ---------------- block1 SPMM (fp16, 8 halves/thread, 8 threads/row) ----------------
template <bool FIRST>
__global__ void __launch_bounds__(256) k_spmm1(int kin, int kp2, int kout,
                                               const float* __restrict__ vals,
                                               const int* __restrict__ cols) {
    int tid = blockIdx.x * 256 + threadIdx.x;  // over VV*8
    int v = tid >> 3, d8 = tid & 7;
    const uint4* tin = (const uint4*)(d_Th + (size_t)kin * VV * 64);  // 8 uint4/row
    float a[8];
#pragma unroll
    for (int i = 0; i < 8; ++i) a[i] = 0.f;
#pragma unroll
    for (int j = 0; j < NNZ; ++j) {
        int c = __ldg(&cols[v * NNZ + j]);
        float w = __ldg(&vals[v * NNZ + j]);
        float t[8];
        h8_to_f8(__ldg(tin + (size_t)c * 8 + d8), t);
#pragma unroll
        for (int i = 0; i < 8; ++i) a[i] += w * t[i];
    }
    if (!FIRST) {
        float p[8];
        h8_to_f8(((const uint4*)(d_Th + (size_t)kp2 * VV * 64))[tid], p);
#pragma unroll
        for (int i = 0; i < 8; ++i) a[i] = 2.f * a[i] - p[i];
    }
    ((uint4*)(d_Th + (size_t)kout * VV * 64))[tid] = f8_to_h8(a);
}

// ---------------- block2 SPMM (fp16, 8 halves/thread, 16 threads/row) ----------------
template <bool FIRST>
__global__ void __launch_bounds__(256) k_spmm2(int kin, int kp2, int kout,
                                               const float* __restrict__ vals,
                                               const int* __restrict__ cols) {
    int tid = blockIdx.x * 256 + threadIdx.x;  // over VV*16
    int v = tid >> 4, d8 = tid & 15;
    const uint4* tin = (const uint4*)(d_Uh + (size_t)kin * VV * 128);  // 16 uint4/row
    float a[8];
#pragma unroll
    for (int i = 0; i < 8; ++i) a[i] = 0.f;
#pragma unroll
    for (int j = 0; j < NNZ; ++j) {
        int c = __ldg(&cols[v * NNZ + j]);
        float w = __ldg(&vals[v * NNZ + j]);
        float t[8];
        h8_to_f8(__ldg(tin + (size_t)c * 16 + d8), t);
#pragma unroll
        for (int i = 0; i < 8; ++i) a[i] += w * t[i];
    }
    if (!FIRST) {
        float p[8];
        h8_to_f8(((const uint4*)(d_Uh + (size_t)kp2 * VV * 128))[tid], p);
#pragma unroll
        for (int i = 0; i < 8; ++i) a[i] = 2.f * a[i] - p[i];
    }
    ((uint4*)(d_Uh + (size_t)kout * VV * 128))[tid] = f8_to_h8(a);
}

// ---------------- GEMM 1: [98304 x 256] @ [256 x 128] (W1|Wr), cp.async pipelined ----------
// Chunk 0 A = x (fp32, manual stage); chunks 1..7 = d_Th fp16 via cp.async.
__global__ void __launch_bounds__(256) k_gemm1_mma(const float* __restrict__ x,
                                                   const float* __restrict__ b1,
                                                   const float* __restrict__ br) {
    extern __shared__ float smem[];
    __half (*As)[128][40] = (__half(*)[128][40])smem;                   // 2 x 10 KB
    float (*Bs)[128][36] = (float(*)[128][36])(smem + 2 * 128 * 40 / 2); // 2 x 18 KB
    int v0 = blockIdx.x * 64;
    int tid = threadIdx.x;
    int warp = tid >> 5, lane = tid & 31;
    int g = lane >> 2, t = lane & 3;
    int wm = warp >> 1, wn = warp & 1;
    int m_w = wm * 32, n_w = wn * 64;

    float acc[2][8][4];
#pragma unroll
    for (int mi = 0; mi < 2; ++mi)
#pragma unroll
        for (int ni = 0; ni < 8; ++ni)
#pragma unroll
            for (int q = 0; q < 4; ++q) acc[mi][ni][q] = 0.f;

    auto stageB = [&](int c, int buf) {
        const float4* bsrc = (const float4*)d_Bt1 + c * 1024;
#pragma unroll
        for (int tl = 0; tl < 4; ++tl) {
            int lt4 = tid + tl * 256;
            int lt = lt4 * 4;
            cpasync16(&Bs[buf][lt >> 5][lt & 31], bsrc + lt4);
        }
    };
    auto stageA = [&](int c, int buf) {
        const __half* asrc = d_Th + (size_t)c * VV * 64 + (size_t)v0 * 64;
#pragma unroll
        for (int tl = 0; tl < 2; ++tl) {
            int lt8 = tid + tl * 256;
            int voff = lt8 >> 3, h0 = (lt8 & 7) * 8;
            int bb = h0 >> 5, f = h0 & 31;
            cpasync16(&As[buf][voff * 2 + bb][f], asrc + voff * 64 + h0);
        }
    };

    {
        const float4* xs = (const float4*)x;
#pragma unroll
        for (int tl = 0; tl < 4; ++tl) {
            int lt4 = tid + tl * 256;
            int voff = lt4 >> 4, bb = (lt4 >> 3) & 1, f4 = lt4 & 7;
            float4 val = xs[((size_t)bb * VV + v0 + voff) * 8 + f4];
            __half2 h0 = __floats2half2_rn(val.x, val.y);
            __half2 h1 = __floats2half2_rn(val.z, val.w);
            uint2 o;
            o.x = *(uint32_t*)&h0; o.y = *(uint32_t*)&h1;
            *(uint2*)&As[0][voff * 2 + bb][f4 * 4] = o;
        }
        stageB(0, 0);
        CP_COMMIT();
    }
#pragma unroll 1
    for (int c = 0; c < 8; ++c) {
        int cb = c & 1;
        if (c < 7) {
            stageA(c + 1, cb ^ 1);
            stageB(c + 1, cb ^ 1);
            CP_COMMIT();
            CP_WAIT(1);
        } else {
            CP_WAIT(0);
        }
        __syncthreads();
#pragma unroll
        for (int ks = 0; ks < 4; ++ks) {
            int k0 = ks * 8;
            uint32_t a[2][4];
#pragma unroll
            for (int mi = 0; mi < 2; ++mi) {
                int m = m_w + mi * 16;
                a[mi][0] = u_tf32(__half2float(As[cb][m + g][k0 + t]));
                a[mi][1] = u_tf32(__half2float(As[cb][m + g + 8][k0 + t]));
                a[mi][2] = u_tf32(__half2float(As[cb][m + g][k0 + t + 4]));
                a[mi][3] = u_tf32(__half2float(As[cb][m + g + 8][k0 + t + 4]));
            }
#pragma unroll
            for (int ni = 0; ni < 8; ++ni) {
                int n = n_w + ni * 8;
                uint32_t b0 = __float_as_uint(Bs[cb][n + g][k0 + t]);
                uint32_t b1v = __float_as_uint(Bs[cb][n + g][k0 + t + 4]);
#pragma unroll
                for (int mi = 0; mi < 2; ++mi)
                    mma_tf32(acc[mi][ni], a[mi][0], a[mi][1], a[mi][2], a[mi][3], b0, b1v);
            }
        }
        __syncthreads();
    }
    // epilogue + fused GN1 stats; h1pre -> d_h1 (fp32), res -> d_res
    float sni[8], s2ni[8];
#pragma unroll
    for (int ni = 0; ni < 8; ++ni) { sni[ni] = 0.f; s2ni[ni] = 0.f; }
#pragma unroll
    for (int mi = 0; mi < 2; ++mi) {
        int r1 = m_w + mi * 16 + g;
        int v1 = v0 + (r1 >> 1), bb1 = r1 & 1;
        int r2 = r1 + 8;
        int v2 = v0 + (r2 >> 1), bb2 = r2 & 1;
#pragma unroll
        for (int ni = 0; ni < 8; ++ni) {
            int n = n_w + ni * 8 + t * 2;
            float2 p1 = make_float2(acc[mi][ni][0], acc[mi][ni][1]);
            float2 p2 = make_float2(acc[mi][ni][2], acc[mi][ni][3]);
            if (n < 64) {
                float bx = __ldg(&b1[n]), by = __ldg(&b1[n + 1]);
                p1.x += bx; p1.y += by; p2.x += bx; p2.y += by;
                *(float2*)(d_h1 + (size_t)v1 * 128 + bb1 * 64 + n) = p1;
                *(float2*)(d_h1 + (size_t)v2 * 128 + bb2 * 64 + n) = p2;
                sni[ni] += p1.x + p1.y + p2.x + p2.y;
                s2ni[ni] += p1.x * p1.x + p1.y * p1.y + p2.x * p2.x + p2.y * p2.y;
            } else {
                int o = n - 64;
                float bx = __ldg(&br[o]), by = __ldg(&br[o + 1]);
                p1.x += bx; p1.y += by; p2.x += bx; p2.y += by;
                *(float2*)(d_res + (size_t)bb1 * VV * 64 + (size_t)v1 * 64 + o) = p1;
                *(float2*)(d_res + (size_t)bb2 * VV * 64 + (size_t)v2 * 64 + o) = p2;
            }
        }
    }
    if (wn == 0) {
        float* sb = d_stats + (blockIdx.x & 7) * 64;
#pragma unroll
        for (int ni = 0; ni < 8; ++ni) {
            float s = sni[ni], s2 = s2ni[ni];
            red_stats(s, s2);
            if ((lane & 0x1B) == 0) {
                int bb = (lane >> 2) & 1;
                atomicAdd(&sb[(bb * 8 + ni) * 2], s);
                atomicAdd(&sb[(bb * 8 + ni) * 2 + 1], s2);
            }
        }
    }
}

// ---------------- GEMM 2: [98304 x 512] @ [512 x 64] (W2), fp16 A, cp.async ------------
__global__ void __launch_bounds__(256) k_gemm2_mma(const float* __restrict__ b2,
                                                   float* __restrict__ out) {
    extern __shared__ float smem[];
    __half (*As)[128][40] = (__half(*)[128][40])smem;                   // 2 x 10 KB
    float (*Bs)[64][36] = (float(*)[64][36])(smem + 2 * 128 * 40 / 2);  // 2 x 9 KB
    int v0 = blockIdx.x * 64;
    int tid = threadIdx.x;
    int warp = tid >> 5, lane = tid & 31;
    int g = lane >> 2, t = lane & 3;
    int m_w = warp * 16;

    float acc[8][4];
#pragma unroll
    for (int ni = 0; ni < 8; ++ni)
#pragma unroll
        for (int q = 0; q < 4; ++q) acc[ni][q] = 0.f;

    auto stage = [&](int c, int buf) {
        int kk = c >> 1, f0 = (c & 1) * 32;
        const __half* asrc = d_Uh + (size_t)kk * VV * 128 + (size_t)v0 * 128 + f0;
#pragma unroll
        for (int tl = 0; tl < 2; ++tl) {
            int q = tid + tl * 256;       // 512 chunks of 8 halves
            int r = q >> 2, p = q & 3;
            cpasync16(&As[buf][r][p * 8], asrc + (r >> 1) * 128 + (r & 1) * 64 + p * 8);
        }
        const float4* bsrc = (const float4*)d_Bt2 + c * 512;
#pragma unroll
        for (int tl = 0; tl < 2; ++tl) {
            int lt4 = tid + tl * 256;
            int lt = lt4 * 4;
            cpasync16(&Bs[buf][lt >> 5][lt & 31], bsrc + lt4);
        }
    };

    stage(0, 0);
    CP_COMMIT();
#pragma unroll 1
    for (int c = 0; c < 16; ++c) {
        int cb = c & 1;
        if (c < 15) {
            stage(c + 1, cb ^ 1);
            CP_COMMIT();
            CP_WAIT(1);
        } else {
            CP_WAIT(0);
        }
        __syncthreads();
#pragma unroll
        for (int ks = 0; ks < 4; ++ks) {
            int k0 = ks * 8;
            uint32_t a0 = u_tf32(__half2float(As[cb][m_w + g][k0 + t]));
            uint32_t a1 = u_tf32(__half2float(As[cb][m_w + g + 8][k0 + t]));
            uint32_t a2 = u_tf32(__half2float(As[cb][m_w + g][k0 + t + 4]));
            uint32_t a3 = u_tf32(__half2float(As[cb][m_w + g + 8][k0 + t + 4]));
#pragma unroll
            for (int ni = 0; ni < 8; ++ni) {
                int n = ni * 8;
                uint32_t b0 = __float_as_uint(Bs[cb][n + g][k0 + t]);
                uint32_t b1v = __float_as_uint(Bs[cb][n + g][k0 + t + 4]);
                mma_tf32(acc[ni], a0, a1, a2, a3, b0, b1v);
            }
        }
        __syncthreads();
    }
    int r1 = m_w + g;
    int v1 = v0 + (r1 >> 1), bb1 = r1 & 1;
    int r2 = r1 + 8;
    int v2 = v0 + (r2 >> 1), bb2 = r2 & 1;
    float* o1 = out + (size_t)bb1 * VV * 64 + (size_t)v1 * 64;
    float* o2 = out + (size_t)bb2 * VV * 64 + (size_t)v2 * 64;
    float* sb = d_stats + (blockIdx.x & 7) * 64;
#pragma unroll
    for (int ni = 0; ni < 8; ++ni) {
        int n = ni * 8 + t * 2;
        float bx = __ldg(&b2[n]), by = __ldg(&b2[n + 1]);
        float e0 = acc[ni][0] + bx, e1 = acc[ni][1] + by;
        float e2 = acc[ni][2] + bx, e3 = acc[ni][3] + by;
        *(float2*)(o1 + n) = make_float2(e0, e1);
        *(float2*)(o2 + n) = make_float2(e2, e3);
        float s = e0 + e1 + e2 + e3;
        float s2 = e0 * e0 + e1 * e1 + e2 * e2 + e3 * e3;
        red_stats(s, s2);
        if ((lane & 0x1B) == 0) {
            int bb = (lane >> 2) & 1;
            atomicAdd(&sb[32 + (bb * 8 + ni) * 2], s);
            atomicAdd(&sb[32 + (bb * 8 + ni) * 2 + 1], s2);
        }
    }
}

// ---------------- GN1 apply + LeakyReLU: d_h1 (fp32) -> d_Uh slot0 (fp16) ----------------
__global__ void __launch_bounds__(256) k_gnapply1(const float* __restrict__ gamma,
                                                  const float* __restrict__ beta) {
    int tid = blockIdx.x * 256 + threadIdx.x;  // over VV*128/4
    int idx = tid * 4;
    int rem = idx & 127, b = rem >> 6, c0 = rem & 63, g = c0 >> 3;
    int bin = (b * 8 + g) * 2;
    float s = 0.f, s2 = 0.f;
#pragma unroll
    for (int p = 0; p < 8; ++p) { s += d_stats[p * 64 + bin]; s2 += d_stats[p * 64 + bin + 1]; }
    float mu = s / GN_N;
    float var = s2 / GN_N - mu * mu;
    float rstd = rsqrtf(var + 1e-5f);
    float4 v = *(const float4*)(d_h1 + idx);
    float y0 = (v.x - mu) * rstd * __ldg(&gamma[c0 + 0]) + __ldg(&beta[c0 + 0]);
    float y1 = (v.y - mu) * rstd * __ldg(&gamma[c0 + 1]) + __ldg(&beta[c0 + 1]);
    float y2 = (v.z - mu) * rstd * __ldg(&gamma[c0 + 2]) + __ldg(&beta[c0 + 2]);
    float y3 = (v.w - mu) * rstd * __ldg(&gamma[c0 + 3]) + __ldg(&beta[c0 + 3]);
    y0 = fmaxf(y0, 0.1f * y0); y1 = fmaxf(y1, 0.1f * y1);
    y2 = fmaxf(y2, 0.1f * y2); y3 = fmaxf(y3, 0.1f * y3);
    __half2 h0 = __floats2half2_rn(y0, y1);
    __half2 h1 = __floats2half2_rn(y2, y3);
    uint2 o;
    o.x = *(uint32_t*)&h0; o.y = *(uint32_t*)&h1;
    *((uint2*)d_Uh + tid) = o;
}

// ---------------- final: out = leaky(GN2(h2pre)) + res, in place ----------------
__global__ void k_final(float* __restrict__ out,
                        const float* __restrict__ gamma, const float* __restrict__ beta) {
    int idx = blockIdx.x * blockDim.x + threadIdx.x;
    if (idx >= 2 * VV * 64) return;
    int b = idx / (VV * 64);
    int c = idx & 63, g = c >> 3;
    int bin = 32 + (b * 8 + g) * 2;
    float s = 0.f, s2 = 0.f;
#pragma unroll
    for (int p = 0; p < 8; ++p) { s += d_stats[p * 64 + bin]; s2 += d_stats[p * 64 + bin + 1]; }
    float mu = s / GN_N;
    float var = s2 / GN_N - mu * mu;
    float rstd = rsqrtf(var + 1e-5f);
    float y = (out[idx] - mu) * rstd * gamma[c] + beta[c];
    out[idx] = fmaxf(y, 0.1f * y) + d_res[idx];
}

// ---------------- launch ----------------
extern "C" void kernel_launch(void* const* d_in, const int* in_sizes, int n_in,
                              void* d_out, int out_size) {
    const float* x    = (const float*)d_in[0];
    const float* vals = (const float*)d_in[1];
    const int*   cols = (const int*)d_in[3];
    const float* W1 = (const float*)d_in[4];
    const float* b1 = (const float*)d_in[5];
    const float* g1 = (const float*)d_in[6];
    const float* be1 = (const float*)d_in[7];
    const float* W2 = (const float*)d_in[8];
    const float* b2 = (const float*)d_in[9];
    const float* g2 = (const float*)d_in[10];
    const float* be2 = (const float*)d_in[11];
    const float* Wr = (const float*)d_in[12];
    const float* br = (const float*)d_in[13];
    float* out = (float*)d_out;

    const int SMEM1 = 2 * 128 * 40 * 2 + 2 * 128 * 36 * 4;  // 57344 B
    const int SMEM2 = 2 * 128 * 40 * 2 + 2 * 64 * 36 * 4;   // 38912 B
    cudaFuncSetAttribute(k_gemm1_mma, cudaFuncAttributeMaxDynamicSharedMemorySize, SMEM1);
    cudaFuncSetAttribute(k_gemm2_mma, cudaFuncAttributeMaxDynamicSharedMemorySize, SMEM2);

    k_wtrans<<<(8 * 128 * 32 + 16 * 64 * 32) / 256, 256>>>(W1, Wr, W2);
    k_xhalf<<<(VV * 16) / 256, 256>>>(x);

    // block1 Chebyshev terms t1..t7 (fp16)
    const int g1d = (VV * 8) / 256;
    k_spmm1<true><<<g1d, 256>>>(0, 0, 1, vals, cols);
    k_spmm1<false><<<g1d, 256>>>(1, 0, 2, vals, cols);
    k_spmm1<false><<<g1d, 256>>>(2, 1, 3, vals, cols);
    k_spmm1<false><<<g1d, 256>>>(3, 2, 4, vals, cols);
    k_spmm1<false><<<g1d, 256>>>(4, 3, 5, vals, cols);
    k_spmm1<false><<<g1d, 256>>>(5, 4, 6, vals, cols);
    k_spmm1<false><<<g1d, 256>>>(6, 5, 7, vals, cols);

    // h1pre (fp32 -> d_h1) + residual + fused GN1 stats
    k_gemm1_mma<<<VV / 64, 256, SMEM1>>>(x, b1, br);

    // GN1 apply: d_h1 -> d_Uh slot0 (fp16)
    k_gnapply1<<<(VV * 128 / 4) / 256, 256>>>(g1, be1);

    // block2 Chebyshev terms u1..u7 (fp16)
    const int g2d = (VV * 16) / 256;
    k_spmm2<true><<<g2d, 256>>>(0, 0, 1, vals, cols);
    k_spmm2<false><<<g2d, 256>>>(1, 0, 2, vals, cols);
    k_spmm2<false><<<g2d, 256>>>(2, 1, 3, vals, cols);
    k_spmm2<false><<<g2d, 256>>>(3, 2, 4, vals, cols);
    k_spmm2<false><<<g2d, 256>>>(4, 3, 5, vals, cols);
    k_spmm2<false><<<g2d, 256>>>(5, 4, 6, vals, cols);
    k_spmm2<false><<<g2d, 256>>>(6, 5, 7, vals, cols);

    // h2pre -> out + fused GN2 stats
    k_gemm2_mma<<<VV / 64, 256, SMEM2>>>(b2, out);

    // GN2 + LeakyReLU + residual add
    k_final<<<(2 * VV * 64) / 256, 256>>>(out, g2, be2);
}

// round 12
// speedup vs baseline: 2.1777x; 1.1647x over previous
#include <cuda_runtime.h>
#include <cuda_fp16.h>
#include <cstdint>

#define VV 49152
#define NNZ 9
#define GN_N 393216.0f  // V * (C/G)

// ---------------- scratch (device globals; no runtime allocation) ----------------
__device__ __half d_Th[(size_t)8 * VV * 64];   // block1 terms fp16: slot0 = x, 1..7 = t1..t7
__device__ __half d_Uh[(size_t)8 * VV * 128];  // block2 terms fp16: slot0 = normalized h1, 1..7
__device__ float d_h1[(size_t)VV * 128];       // raw h1pre fp32 (GEMM1 out)
__device__ float d_res[(size_t)2 * VV * 64];   // residual conv output [b][v][o]
__device__ float d_stats[8 * 64];              // 8 spread buffers x [GN1 | GN2] (sum,sumsq)x16
__device__ __half d_Bt1h[8 * 128 * 32];        // GEMM1 B^T (W1|Wr) fp16
__device__ __half d_Bt2h[16 * 64 * 32];        // GEMM2 B^T (W2) fp16
__device__ int4 d_colp4[VV * 3];               // padded cols: 12 per row
__device__ float4 d_valp4[VV * 3];             // padded vals: 12 per row

// ---------------- helpers ----------------
__device__ __forceinline__ void mma_f16(float* d, uint32_t a0, uint32_t a1, uint32_t a2,
                                        uint32_t a3, uint32_t b0, uint32_t b1) {
    asm volatile(
        "mma.sync.aligned.m16n8k16.row.col.f32.f16.f16.f32 "
        "{%0,%1,%2,%3}, {%4,%5,%6,%7}, {%8,%9}, {%0,%1,%2,%3};"
        : "+f"(d[0]), "+f"(d[1]), "+f"(d[2]), "+f"(d[3])
        : "r"(a0), "r"(a1), "r"(a2), "r"(a3), "r"(b0), "r"(b1));
}
__device__ __forceinline__ void cpasync16(void* sptr, const void* gptr) {
    uint32_t sa = (uint32_t)__cvta_generic_to_shared(sptr);
    asm volatile("cp.async.cg.shared.global [%0], [%1], 16;" :: "r"(sa), "l"(gptr));
}
#define CP_COMMIT() asm volatile("cp.async.commit_group;" ::: "memory")
#define CP_WAIT(n)  asm volatile("cp.async.wait_group %0;" :: "n"(n) : "memory")

__device__ __forceinline__ void red_stats(float& s, float& s2) {
#pragma unroll
    for (int m = 1; m <= 16; m <<= 1) {
        if (m == 4) continue;
        s += __shfl_xor_sync(0xFFFFFFFFu, s, m);
        s2 += __shfl_xor_sync(0xFFFFFFFFu, s2, m);
    }
}
__device__ __forceinline__ void h8_to_f8(uint4 hv, float* f) {
    float2 q0 = __half22float2(*(__half2*)&hv.x);
    float2 q1 = __half22float2(*(__half2*)&hv.y);
    float2 q2 = __half22float2(*(__half2*)&hv.z);
    float2 q3 = __half22float2(*(__half2*)&hv.w);
    f[0] = q0.x; f[1] = q0.y; f[2] = q1.x; f[3] = q1.y;
    f[4] = q2.x; f[5] = q2.y; f[6] = q3.x; f[7] = q3.y;
}
__device__ __forceinline__ uint4 f8_to_h8(const float* f) {
    uint4 o;
    __half2 h0 = __floats2half2_rn(f[0], f[1]);
    __half2 h1 = __floats2half2_rn(f[2], f[3]);
    __half2 h2 = __floats2half2_rn(f[4], f[5]);
    __half2 h3 = __floats2half2_rn(f[6], f[7]);
    o.x = *(uint32_t*)&h0; o.y = *(uint32_t*)&h1;
    o.z = *(uint32_t*)&h2; o.w = *(uint32_t*)&h3;
    return o;
}
// load padded (cols, vals) for row v
__device__ __forceinline__ void load_adj(int v, int* c9, float* w9) {
    const int4* cp = d_colp4 + v * 3;
    int4 ca = __ldg(cp), cb = __ldg(cp + 1), cc = __ldg(cp + 2);
    const float4* wp = d_valp4 + v * 3;
    float4 wa = __ldg(wp), wb = __ldg(wp + 1), wc = __ldg(wp + 2);
    c9[0] = ca.x; c9[1] = ca.y; c9[2] = ca.z; c9[3] = ca.w;
    c9[4] = cb.x; c9[5] = cb.y; c9[6] = cb.z; c9[7] = cb.w; c9[8] = cc.x;
    w9[0] = wa.x; w9[1] = wa.y; w9[2] = wa.z; w9[3] = wa.w;
    w9[4] = wb.x; w9[5] = wb.y; w9[6] = wb.z; w9[7] = wb.w; w9[8] = wc.x;
}

// ---------------- one-time prep: stats zero, weights fp16, adjacency pad, x fp16 ----------
__global__ void __launch_bounds__(256) k_prep(const float* __restrict__ x,
                                              const float* __restrict__ vals,
                                              const int* __restrict__ cols,
                                              const float* __restrict__ W1,
                                              const float* __restrict__ Wr,
                                              const float* __restrict__ W2) {
    int idx = blockIdx.x * 256 + threadIdx.x;
    if (idx < 512) { d_stats[idx] = 0.0f; return; }
    idx -= 512;
    if (idx < 32768) {  // Bt1h [kk][o][f]
        int kk = idx >> 12, r = idx & 4095, o = r >> 5, f = r & 31;
        float w = (o < 64) ? W1[kk * 2048 + f * 64 + o] : Wr[kk * 2048 + f * 64 + (o - 64)];
        d_Bt1h[idx] = __float2half(w);
        return;
    }
    idx -= 32768;
    if (idx < 32768) {  // Bt2h [c][o][f]
        int c = idx >> 11, rr = idx & 2047, o = rr >> 5, f = rr & 31;
        int kk = c >> 1, f0 = (c & 1) * 32;
        d_Bt2h[idx] = __float2half(W2[kk * 4096 + (f0 + f) * 64 + o]);
        return;
    }
    idx -= 32768;
    if (idx < VV * 3) {  // cols pad
        int v = idx / 3, j = (idx % 3) * 4;
        int4 o;
        o.x = cols[v * 9 + j];
        o.y = (j + 1 < 9) ? cols[v * 9 + j + 1] : 0;
        o.z = (j + 2 < 9) ? cols[v * 9 + j + 2] : 0;
        o.w = (j + 3 < 9) ? cols[v * 9 + j + 3] : 0;
        d_colp4[idx] = o;
        return;
    }
    idx -= VV * 3;
    if (idx < VV * 3) {  // vals pad
        int v = idx / 3, j = (idx % 3) * 4;
        float4 o;
        o.x = vals[v * 9 + j];
        o.y = (j + 1 < 9) ? vals[v * 9 + j + 1] : 0.f;
        o.z = (j + 2 < 9) ? vals[v * 9 + j + 2] : 0.f;
        o.w = (j + 3 < 9) ? vals[v * 9 + j + 3] : 0.f;
        d_valp4[idx] = o;
        return;
    }
    idx -= VV * 3;
    if (idx < VV * 16) {  // x -> fp16 into d_Th slot0 [v][b*32+f]
        int v = idx >> 4, d = (idx & 15) * 4;
        int b = d >> 5, f = d & 31;
        float4 val = ((const float4*)x)[((size_t)b * VV + v) * 8 + (f >> 2)];
        __half2 h0 = __floats2half2_rn(val.x, val.y);
        __half2 h1 = __floats2half2_rn(val.z, val.w);
        uint2 o;
        o.x = *(uint32_t*)&h0; o.y = *(uint32_t*)&h1;
        *((uint2*)(d_Th) + idx) = o;
    }
}

// ---------------- block1 SPMM (fp16, 8 halves/thread, 8 threads/row) ----------------
template <bool FIRST>
__global__ void __launch_bounds__(256) k_spmm1(int kin, int kp2, int kout,
                                               const float* __restrict__ vals_unused,
                                               const int* __restrict__ cols_unused) {
    int tid = blockIdx.x * 256 + threadIdx.x;  // over VV*8
    int v = tid >> 3, d8 = tid & 7;
    int c9[9]; float w9[9];
    load_adj(v, c9, w9);
    const uint4* tin = (const uint4*)(d_Th + (size_t)kin * VV * 64);
    float a[8];
#pragma unroll
    for (int i = 0; i < 8; ++i) a[i] = 0.f;
#pragma unroll
    for (int j = 0; j < NNZ; ++j) {
        float t[8];
        h8_to_f8(__ldg(tin + (size_t)c9[j] * 8 + d8), t);
#pragma unroll
        for (int i = 0; i < 8; ++i) a[i] += w9[j] * t[i];
    }
    if (!FIRST) {
        float p[8];
        h8_to_f8(((const uint4*)(d_Th + (size_t)kp2 * VV * 64))[tid], p);
#pragma unroll
        for (int i = 0; i < 8; ++i) a[i] = 2.f * a[i] - p[i];
    }
    ((uint4*)(d_Th + (size_t)kout * VV * 64))[tid] = f8_to_h8(a);
}

// ---------------- block2 SPMM (fp16, 8 halves/thread, 16 threads/row) ----------------
template <bool FIRST>
__global__ void __launch_bounds__(256) k_spmm2(int kin, int kp2, int kout,
                                               const float* __restrict__ vals_unused,
                                               const int* __restrict__ cols_unused) {
    int tid = blockIdx.x * 256 + threadIdx.x;  // over VV*16
    int v = tid >> 4, d8 = tid & 15;
    int c9[9]; float w9[9];
    load_adj(v, c9, w9);
    const uint4* tin = (const uint4*)(d_Uh + (size_t)kin * VV * 128);
    float a[8];
#pragma unroll
    for (int i = 0; i < 8; ++i) a[i] = 0.f;
#pragma unroll
    for (int j = 0; j < NNZ; ++j) {
        float t[8];
        h8_to_f8(__ldg(tin + (size_t)c9[j] * 16 + d8), t);
#pragma unroll
        for (int i = 0; i < 8; ++i) a[i] += w9[j] * t[i];
    }
    if (!FIRST) {
        float p[8];
        h8_to_f8(((const uint4*)(d_Uh + (size_t)kp2 * VV * 128))[tid], p);
#pragma unroll
        for (int i = 0; i < 8; ++i) a[i] = 2.f * a[i] - p[i];
    }
    ((uint4*)(d_Uh + (size_t)kout * VV * 128))[tid] = f8_to_h8(a);
}

// ---------------- GEMM 1: [98304 x 256] @ [256 x 128] (W1|Wr), fp16 mma, 3-stage ---------
__global__ void __launch_bounds__(256) k_gemm1_mma(const float* __restrict__ x,
                                                   const float* __restrict__ b1,
                                                   const float* __restrict__ br) {
    extern __shared__ __align__(16) char smem[];
    __half (*As)[128][40] = (__half(*)[128][40])smem;              // 3 x 10240 B
    __half (*Bs)[128][40] = (__half(*)[128][40])(smem + 30720);    // 3 x 10240 B
    int v0 = blockIdx.x * 64;
    int tid = threadIdx.x;
    int warp = tid >> 5, lane = tid & 31;
    int g = lane >> 2, t = lane & 3;
    int wm = warp >> 1, wn = warp & 1;
    int m_w = wm * 32, n_w = wn * 64;

    float acc[2][8][4];
#pragma unroll
    for (int mi = 0; mi < 2; ++mi)
#pragma unroll
        for (int ni = 0; ni < 8; ++ni)
#pragma unroll
            for (int q = 0; q < 4; ++q) acc[mi][ni][q] = 0.f;

    auto stageB = [&](int c, int buf) {
        const __half* bsrc = d_Bt1h + c * 4096;
#pragma unroll
        for (int tl = 0; tl < 2; ++tl) {
            int q = tid + tl * 256;  // 512 chunks of 8 halves
            int o = q >> 2, p = q & 3;
            cpasync16(&Bs[buf][o][p * 8], bsrc + o * 32 + p * 8);
        }
    };
    auto stageA = [&](int c, int buf) {  // c >= 1
        const __half* asrc = d_Th + (size_t)c * VV * 64 + (size_t)v0 * 64;
#pragma unroll
        for (int tl = 0; tl < 2; ++tl) {
            int q = tid + tl * 256;
            int r = q >> 2, p = q & 3;
            cpasync16(&As[buf][r][p * 8], asrc + (r >> 1) * 64 + (r & 1) * 32 + p * 8);
        }
    };

    // prologue: chunk0 A = x (fp32 -> half manual); stage B0; stage A1+B1
    {
        const float4* xs = (const float4*)x;
#pragma unroll
        for (int tl = 0; tl < 4; ++tl) {
            int lt4 = tid + tl * 256;
            int voff = lt4 >> 4, bb = (lt4 >> 3) & 1, f4 = lt4 & 7;
            float4 val = xs[((size_t)bb * VV + v0 + voff) * 8 + f4];
            __half2 h0 = __floats2half2_rn(val.x, val.y);
            __half2 h1 = __floats2half2_rn(val.z, val.w);
            uint2 o;
            o.x = *(uint32_t*)&h0; o.y = *(uint32_t*)&h1;
            *(uint2*)&As[0][voff * 2 + bb][f4 * 4] = o;
        }
        stageB(0, 0);
        CP_COMMIT();
        stageA(1, 1); stageB(1, 1);
        CP_COMMIT();
    }
#pragma unroll 1
    for (int c = 0; c < 8; ++c) {
        int cb = c - (c / 3) * 3;  // c % 3
        if (c < 6) {
            int nb = (c + 2) - ((c + 2) / 3) * 3;
            stageA(c + 2, nb); stageB(c + 2, nb);
            CP_COMMIT();
            CP_WAIT(2);
        } else if (c == 6) {
            CP_WAIT(1);
        } else {
            CP_WAIT(0);
        }
        __syncthreads();
#pragma unroll
        for (int ks = 0; ks < 2; ++ks) {
            int k0 = ks * 16;
            uint32_t a[2][4];
#pragma unroll
            for (int mi = 0; mi < 2; ++mi) {
                int m = m_w + mi * 16;
                a[mi][0] = *(uint32_t*)&As[cb][m + g][k0 + 2 * t];
                a[mi][1] = *(uint32_t*)&As[cb][m + g + 8][k0 + 2 * t];
                a[mi][2] = *(uint32_t*)&As[cb][m + g][k0 + 2 * t + 8];
                a[mi][3] = *(uint32_t*)&As[cb][m + g + 8][k0 + 2 * t + 8];
            }
#pragma unroll
            for (int ni = 0; ni < 8; ++ni) {
                int n = n_w + ni * 8;
                uint32_t b0 = *(uint32_t*)&Bs[cb][n + g][k0 + 2 * t];
                uint32_t b1v = *(uint32_t*)&Bs[cb][n + g][k0 + 2 * t + 8];
#pragma unroll
                for (int mi = 0; mi < 2; ++mi)
                    mma_f16(acc[mi][ni], a[mi][0], a[mi][1], a[mi][2], a[mi][3], b0, b1v);
            }
        }
        __syncthreads();
    }
    // epilogue + fused GN1 stats; h1pre -> d_h1 (fp32), res -> d_res
    float sni[8], s2ni[8];
#pragma unroll
    for (int ni = 0; ni < 8; ++ni) { sni[ni] = 0.f; s2ni[ni] = 0.f; }
#pragma unroll
    for (int mi = 0; mi < 2; ++mi) {
        int r1 = m_w + mi * 16 + g;
        int v1 = v0 + (r1 >> 1), bb1 = r1 & 1;
        int r2 = r1 + 8;
        int v2 = v0 + (r2 >> 1), bb2 = r2 & 1;
#pragma unroll
        for (int ni = 0; ni < 8; ++ni) {
            int n = n_w + ni * 8 + t * 2;
            float2 p1 = make_float2(acc[mi][ni][0], acc[mi][ni][1]);
            float2 p2 = make_float2(acc[mi][ni][2], acc[mi][ni][3]);
            if (n < 64) {
                float bx = __ldg(&b1[n]), by = __ldg(&b1[n + 1]);
                p1.x += bx; p1.y += by; p2.x += bx; p2.y += by;
                *(float2*)(d_h1 + (size_t)v1 * 128 + bb1 * 64 + n) = p1;
                *(float2*)(d_h1 + (size_t)v2 * 128 + bb2 * 64 + n) = p2;
                sni[ni] += p1.x + p1.y + p2.x + p2.y;
                s2ni[ni] += p1.x * p1.x + p1.y * p1.y + p2.x * p2.x + p2.y * p2.y;
            } else {
                int o = n - 64;
                float bx = __ldg(&br[o]), by = __ldg(&br[o + 1]);
                p1.x += bx; p1.y += by; p2.x += bx; p2.y += by;
                *(float2*)(d_res + (size_t)bb1 * VV * 64 + (size_t)v1 * 64 + o) = p1;
                *(float2*)(d_res + (size_t)bb2 * VV * 64 + (size_t)v2 * 64 + o) = p2;
            }
        }
    }
    if (wn == 0) {
        float* sb = d_stats + (blockIdx.x & 7) * 64;
#pragma unroll
        for (int ni = 0; ni < 8; ++ni) {
            float s = sni[ni], s2 = s2ni[ni];
            red_stats(s, s2);
            if ((lane & 0x1B) == 0) {
                int bb = (lane >> 2) & 1;
                atomicAdd(&sb[(bb * 8 + ni) * 2], s);
                atomicAdd(&sb[(bb * 8 + ni) * 2 + 1], s2);
            }
        }
    }
}

// ---------------- GEMM 2: [98304 x 512] @ [512 x 64] (W2), fp16 mma, 3-stage -------------
__global__ void __launch_bounds__(256) k_gemm2_mma(const float* __restrict__ b2,
                                                   float* __restrict__ out) {
    extern __shared__ __align__(16) char smem[];
    __half (*As)[128][40] = (__half(*)[128][40])smem;              // 3 x 10240 B
    __half (*Bs)[64][40] = (__half(*)[64][40])(smem + 30720);      // 3 x 5120 B
    int v0 = blockIdx.x * 64;
    int tid = threadIdx.x;
    int warp = tid >> 5, lane = tid & 31;
    int g = lane >> 2, t = lane & 3;
    int m_w = warp * 16;

    float acc[8][4];
#pragma unroll
    for (int ni = 0; ni < 8; ++ni)
#pragma unroll
        for (int q = 0; q < 4; ++q) acc[ni][q] = 0.f;

    auto stage = [&](int c, int buf) {
        int kk = c >> 1, f0 = (c & 1) * 32;
        const __half* asrc = d_Uh + (size_t)kk * VV * 128 + (size_t)v0 * 128 + f0;
#pragma unroll
        for (int tl = 0; tl < 2; ++tl) {
            int q = tid + tl * 256;
            int r = q >> 2, p = q & 3;
            cpasync16(&As[buf][r][p * 8], asrc + (r >> 1) * 128 + (r & 1) * 64 + p * 8);
        }
        const __half* bsrc = d_Bt2h + c * 2048;
        {
            int q = tid;  // 256 chunks of 8 halves
            int o = q >> 2, p = q & 3;
            cpasync16(&Bs[buf][o][p * 8], bsrc + o * 32 + p * 8);
        }
    };

    stage(0, 0); CP_COMMIT();
    stage(1, 1); CP_COMMIT();
#pragma unroll 1
    for (int c = 0; c < 16; ++c) {
        int cb = c - (c / 3) * 3;
        if (c < 14) {
            int nb = (c + 2) - ((c + 2) / 3) * 3;
            stage(c + 2, nb);
            CP_COMMIT();
            CP_WAIT(2);
        } else if (c == 14) {
            CP_WAIT(1);
        } else {
            CP_WAIT(0);
        }
        __syncthreads();
#pragma unroll
        for (int ks = 0; ks < 2; ++ks) {
            int k0 = ks * 16;
            uint32_t a0 = *(uint32_t*)&As[cb][m_w + g][k0 + 2 * t];
            uint32_t a1 = *(uint32_t*)&As[cb][m_w + g + 8][k0 + 2 * t];
            uint32_t a2 = *(uint32_t*)&As[cb][m_w + g][k0 + 2 * t + 8];
            uint32_t a3 = *(uint32_t*)&As[cb][m_w + g + 8][k0 + 2 * t + 8];
#pragma unroll
            for (int ni = 0; ni < 8; ++ni) {
                int n = ni * 8;
                uint32_t b0 = *(uint32_t*)&Bs[cb][n + g][k0 + 2 * t];
                uint32_t b1v = *(uint32_t*)&Bs[cb][n + g][k0 + 2 * t + 8];
                mma_f16(acc[ni], a0, a1, a2, a3, b0, b1v);
            }
        }
        __syncthreads();
    }
    int r1 = m_w + g;
    int v1 = v0 + (r1 >> 1), bb1 = r1 & 1;
    int r2 = r1 + 8;
    int v2 = v0 + (r2 >> 1), bb2 = r2 & 1;
    float* o1 = out + (size_t)bb1 * VV * 64 + (size_t)v1 * 64;
    float* o2 = out + (size_t)bb2 * VV * 64 + (size_t)v2 * 64;
    float* sb = d_stats + (blockIdx.x & 7) * 64;
#pragma unroll
    for (int ni = 0; ni < 8; ++ni) {
        int n = ni * 8 + t * 2;
        float bx = __ldg(&b2[n]), by = __ldg(&b2[n + 1]);
        float e0 = acc[ni][0] + bx, e1 = acc[ni][1] + by;
        float e2 = acc[ni][2] + bx, e3 = acc[ni][3] + by;
        *(float2*)(o1 + n) = make_float2(e0, e1);
        *(float2*)(o2 + n) = make_float2(e2, e3);
        float s = e0 + e1 + e2 + e3;
        float s2 = e0 * e0 + e1 * e1 + e2 * e2 + e3 * e3;
        red_stats(s, s2);
        if ((lane & 0x1B) == 0) {
            int bb = (lane >> 2) & 1;
            atomicAdd(&sb[32 + (bb * 8 + ni) * 2], s);
            atomicAdd(&sb[32 + (bb * 8 + ni) * 2 + 1], s2);
        }
    }
}

// ---------------- GN1 apply + LeakyReLU: d_h1 (fp32) -> d_Uh slot0 (fp16) ----------------
__global__ void __launch_bounds__(256) k_gnapply1(const float* __restrict__ gamma,
                                                  const float* __restrict__ beta) {
    int tid = blockIdx.x * 256 + threadIdx.x;  // over VV*128/4
    int idx = tid * 4;
    int rem = idx & 127, b = rem >> 6, c0 = rem & 63, g = c0 >> 3;
    int bin = (b * 8 + g) * 2;
    float s = 0.f, s2 = 0.f;
#pragma unroll
    for (int p = 0; p < 8; ++p) { s += d_stats[p * 64 + bin]; s2 += d_stats[p * 64 + bin + 1]; }
    float mu = s / GN_N;
    float var = s2 / GN_N - mu * mu;
    float rstd = rsqrtf(var + 1e-5f);
    float4 v = *(const float4*)(d_h1 + idx);
    float y0 = (v.x - mu) * rstd * __ldg(&gamma[c0 + 0]) + __ldg(&beta[c0 + 0]);
    float y1 = (v.y - mu) * rstd * __ldg(&gamma[c0 + 1]) + __ldg(&beta[c0 + 1]);
    float y2 = (v.z - mu) * rstd * __ldg(&gamma[c0 + 2]) + __ldg(&beta[c0 + 2]);
    float y3 = (v.w - mu) * rstd * __ldg(&gamma[c0 + 3]) + __ldg(&beta[c0 + 3]);
    y0 = fmaxf(y0, 0.1f * y0); y1 = fmaxf(y1, 0.1f * y1);
    y2 = fmaxf(y2, 0.1f * y2); y3 = fmaxf(y3, 0.1f * y3);
    __half2 h0 = __floats2half2_rn(y0, y1);
    __half2 h1 = __floats2half2_rn(y2, y3);
    uint2 o;
    o.x = *(uint32_t*)&h0; o.y = *(uint32_t*)&h1;
    *((uint2*)d_Uh + tid) = o;
}

// ---------------- final: out = leaky(GN2(h2pre)) + res (float4) ----------------
__global__ void __launch_bounds__(256) k_final(float* __restrict__ out,
                                               const float* __restrict__ gamma,
                                               const float* __restrict__ beta) {
    int tid = blockIdx.x * 256 + threadIdx.x;  // over 2*VV*16
    int idx = tid * 4;
    int b = (idx >= VV * 64) ? 1 : 0;
    int c0 = idx & 63, g = c0 >> 3;
    int bin = 32 + (b * 8 + g) * 2;
    float s = 0.f, s2 = 0.f;
#pragma unroll
    for (int p = 0; p < 8; ++p) { s += d_stats[p * 64 + bin]; s2 += d_stats[p * 64 + bin + 1]; }
    float mu = s / GN_N;
    float var = s2 / GN_N - mu * mu;
    float rstd = rsqrtf(var + 1e-5f);
    float4 v = *(const float4*)(out + idx);
    float4 r = *(const float4*)(d_res + idx);
    float y0 = (v.x - mu) * rstd * __ldg(&gamma[c0 + 0]) + __ldg(&beta[c0 + 0]);
    float y1 = (v.y - mu) * rstd * __ldg(&gamma[c0 + 1]) + __ldg(&beta[c0 + 1]);
    float y2 = (v.z - mu) * rstd * __ldg(&gamma[c0 + 2]) + __ldg(&beta[c0 + 2]);
    float y3 = (v.w - mu) * rstd * __ldg(&gamma[c0 + 3]) + __ldg(&beta[c0 + 3]);
    float4 o;
    o.x = fmaxf(y0, 0.1f * y0) + r.x;
    o.y = fmaxf(y1, 0.1f * y1) + r.y;
    o.z = fmaxf(y2, 0.1f * y2) + r.z;
    o.w = fmaxf(y3, 0.1f * y3) + r.w;
    *(float4*)(out + idx) = o;
}

// ---------------- launch ----------------
extern "C" void kernel_launch(void* const* d_in, const int* in_sizes, int n_in,
                              void* d_out, int out_size) {
    const float* x    = (const float*)d_in[0];
    const float* vals = (const float*)d_in[1];
    const int*   cols = (const int*)d_in[3];
    const float* W1 = (const float*)d_in[4];
    const float* b1 = (const float*)d_in[5];
    const float* g1 = (const float*)d_in[6];
    const float* be1 = (const float*)d_in[7];
    const float* W2 = (const float*)d_in[8];
    const float* b2 = (const float*)d_in[9];
    const float* g2 = (const float*)d_in[10];
    const float* be2 = (const float*)d_in[11];
    const float* Wr = (const float*)d_in[12];
    const float* br = (const float*)d_in[13];
    float* out = (float*)d_out;

    const int SMEM1 = 3 * 128 * 40 * 2 * 2;               // 61440 B (A + B)
    const int SMEM2 = 3 * 128 * 40 * 2 + 3 * 64 * 40 * 2; // 46080 B
    cudaFuncSetAttribute(k_gemm1_mma, cudaFuncAttributeMaxDynamicSharedMemorySize, SMEM1);
    cudaFuncSetAttribute(k_gemm2_mma, cudaFuncAttributeMaxDynamicSharedMemorySize, SMEM2);

    const int prep_total = 512 + 32768 + 32768 + VV * 3 + VV * 3 + VV * 16;
    k_prep<<<(prep_total + 255) / 256, 256>>>(x, vals, cols, W1, Wr, W2);

    // block1 Chebyshev terms t1..t7 (fp16)
    const int g1d = (VV * 8) / 256;
    k_spmm1<true><<<g1d, 256>>>(0, 0, 1, vals, cols);
    k_spmm1<false><<<g1d, 256>>>(1, 0, 2, vals, cols);
    k_spmm1<false><<<g1d, 256>>>(2, 1, 3, vals, cols);
    k_spmm1<false><<<g1d, 256>>>(3, 2, 4, vals, cols);
    k_spmm1<false><<<g1d, 256>>>(4, 3, 5, vals, cols);
    k_spmm1<false><<<g1d, 256>>>(5, 4, 6, vals, cols);
    k_spmm1<false><<<g1d, 256>>>(6, 5, 7, vals, cols);

    // h1pre (fp32 -> d_h1) + residual + fused GN1 stats
    k_gemm1_mma<<<VV / 64, 256, SMEM1>>>(x, b1, br);

    // GN1 apply: d_h1 -> d_Uh slot0 (fp16)
    k_gnapply1<<<(VV * 128 / 4) / 256, 256>>>(g1, be1);

    // block2 Chebyshev terms u1..u7 (fp16)
    const int g2d = (VV * 16) / 256;
    k_spmm2<true><<<g2d, 256>>>(0, 0, 1, vals, cols);
    k_spmm2<false><<<g2d, 256>>>(1, 0, 2, vals, cols);
    k_spmm2<false><<<g2d, 256>>>(2, 1, 3, vals, cols);
    k_spmm2<false><<<g2d, 256>>>(3, 2, 4, vals, cols);
    k_spmm2<false><<<g2d, 256>>>(4, 3, 5, vals, cols);
    k_spmm2<false><<<g2d, 256>>>(5, 4, 6, vals, cols);
    k_spmm2<false><<<g2d, 256>>>(6, 5, 7, vals, cols);

    // h2pre -> out + fused GN2 stats
    k_gemm2_mma<<<VV / 64, 256, SMEM2>>>(b2, out);

    // GN2 + LeakyReLU + residual add
    k_final<<<(2 * VV * 16) / 256, 256>>>(out, g2, be2);
}